// round 4
// baseline (speedup 1.0000x reference)
#include <cuda_runtime.h>
#include <math.h>

#define N_PTS 8192
#define S_PTS 4096
#define KNN   16
#define TILE  2048

// ---------------- scratch (__device__ globals; no allocation allowed) ----------------
__device__ float4 g_pts[N_PTS];        // x,y,z,sq for original points
__device__ float4 g_pts_s[S_PTS];      // x,y,z,sq for sampled points
__device__ int    g_ai_before[S_PTS * 4];   // anchors (global idx) for sampled rows
__device__ float  g_intra_before[S_PTS * 6];
__device__ int    g_ni_after[S_PTS * KNN];
__device__ float  g_intra_after[S_PTS * 6];
__device__ float  g_adf[S_PTS * 28];
__device__ float  g_yw[S_PTS * 64];
__device__ float  g_yb[S_PTS * 64];
__device__ float  g_fm[S_PTS * 64];
__device__ float  g_z[S_PTS * 128];
__device__ float  g_stats1[4 * 64];    // mu_w | rs_w | mu_b | rs_b
__device__ float  g_stats2[2 * 128];   // mu_o | rs_o

// ---------------- reference-rounding helpers ----------------
// sq: XLA reduce of x*x over c: ((x^2 + y^2) + z^2), rn each op, no contraction
__device__ __forceinline__ float sq_ref(float x, float y, float z) {
    return __fadd_rn(__fadd_rn(__fmul_rn(x, x), __fmul_rn(y, y)), __fmul_rn(z, z));
}
// dot: cuBLAS SGEMM K=3 fma-accumulation chain, ascending k, acc0 = rn(x*x')
// d2:  XLA elementwise fusion: (sq_i + sq_j) - (2*dot), rn each op
__device__ __forceinline__ float d2_ref(float4 a, float4 b) {
    float dot = fmaf(a.z, b.z, fmaf(a.y, b.y, __fmul_rn(a.x, b.x)));
    float d2  = __fsub_rn(__fadd_rn(a.w, b.w), __fmul_rn(2.0f, dot));
    return fmaxf(d2, 0.0f);
}
__device__ __forceinline__ float d_ref(float4 a, float4 b) {
    float d2 = d2_ref(a, b);
    return d2 > 0.0f ? __fsqrt_rn(d2) : 0.0f;
}
__device__ __forceinline__ float leaky(float v) {
    return v >= 0.0f ? v : 0.2f * v;
}

// ---------------- prep: pack points, gather sampled, emit xyz_s ----------------
__global__ void prep_kernel(const float* __restrict__ xyz,
                            const int* __restrict__ si,
                            float* __restrict__ out_xyz_s) {
    int i = blockIdx.x * blockDim.x + threadIdx.x;
    if (i < N_PTS) {
        float x = xyz[3 * i], y = xyz[3 * i + 1], z = xyz[3 * i + 2];
        g_pts[i] = make_float4(x, y, z, sq_ref(x, y, z));
    }
    if (i < S_PTS) {
        int g = si[i];
        float x = xyz[3 * g], y = xyz[3 * g + 1], z = xyz[3 * g + 2];
        g_pts_s[i] = make_float4(x, y, z, sq_ref(x, y, z));
        out_xyz_s[3 * i]     = x;
        out_xyz_s[3 * i + 1] = y;
        out_xyz_s[3 * i + 2] = z;
    }
}

// ---------------- KNN: thread-per-query over smem candidate tiles ----------------
// Selection in sqrt(D) domain, tie -> lower index (ascending scan + strict-< insert),
// matching jax.lax.top_k(-D). Conservative FMA prefilter (margin 1e-3 >> |fma - ref|
// rounding gap ~2e-6 absolute) guarantees a superset; survivors re-evaluated exactly.
//
// AFTER=true : candidates = g_pts_s (4096), K=16, writes ni_after(+float) & intra_after
// AFTER=false: candidates = g_pts   (8192), K=4,  writes ai_before & intra_before
// Queries are always the sampled rows (only rows the before-graph ever feeds).
template <int K, int NC, bool AFTER>
__global__ void __launch_bounds__(256) knn_kernel(float* __restrict__ out_ni_f) {
    const float4* __restrict__ cand = AFTER ? g_pts_s : g_pts;
    const int q = blockIdx.x * 256 + threadIdx.x;   // always < S_PTS (grid exact)
    float4 qp = g_pts_s[q];

    float ld[K]; int li[K];
#pragma unroll
    for (int r = 0; r < K; r++) { ld[r] = 3.4e38f; li[r] = 0x7fffffff; }
    float thrf = 3.4e38f;

    __shared__ float4 tile[TILE];
    for (int base = 0; base < NC; base += TILE) {
        __syncthreads();
        for (int t = threadIdx.x; t < TILE; t += 256) tile[t] = cand[base + t];
        __syncthreads();
#pragma unroll 4
        for (int t = 0; t < TILE; t++) {
            float4 cp = tile[t];
            float dotf = fmaf(qp.z, cp.z, fmaf(qp.y, cp.y, qp.x * cp.x));
            float d2f  = fmaf(-2.0f, dotf, qp.w + cp.w);
            if (d2f < thrf) {
                // exact reference arithmetic
                float d = d_ref(qp, cp);
                if (d < ld[K - 1]) {
                    float v = d; int vi = base + t;
#pragma unroll
                    for (int r = 0; r < K; r++) {
                        if (v < ld[r]) {
                            float tv = ld[r]; ld[r] = v; v = tv;
                            int   ti = li[r]; li[r] = vi; vi = ti;
                        }
                    }
                    thrf = fmaf(ld[K - 1], ld[K - 1], 1e-3f);
                }
            }
        }
    }

    if (AFTER) {
#pragma unroll
        for (int r = 0; r < K; r++) {
            g_ni_after[q * K + r] = li[r];
            out_ni_f[q * K + r]   = (float)li[r];
        }
    } else {
#pragma unroll
        for (int r = 0; r < 4; r++) g_ai_before[q * 4 + r] = li[r];
    }
    float4 A1 = cand[li[1]], A2 = cand[li[2]], A3 = cand[li[3]];
    float* intra = AFTER ? (g_intra_after + q * 6) : (g_intra_before + q * 6);
    intra[0] = ld[1];
    intra[1] = ld[2];
    intra[2] = ld[3];
    intra[3] = d_ref(A1, A2);
    intra[4] = d_ref(A1, A3);
    intra[5] = d_ref(A2, A3);
}

// ---------------- rf_after: (S,16,28) = [center(6) | intra[nb](6) | inter(16)] ----------------
__global__ void rf_kernel(float* __restrict__ out_rf) {
    int i = blockIdx.x * blockDim.x + threadIdx.x;
    if (i >= S_PTS * KNN) return;
    int n = i >> 4, k = i & 15;
    int nb = g_ni_after[n * KNN + k];
    float* o = out_rf + (size_t)i * 28;
#pragma unroll
    for (int c = 0; c < 6; c++) o[c]     = g_intra_after[n * 6 + c];
#pragma unroll
    for (int c = 0; c < 6; c++) o[6 + c] = g_intra_after[nb * 6 + c];
    float4 P[4], Q[4];
#pragma unroll
    for (int p = 0; p < 4; p++) P[p] = g_pts_s[g_ni_after[n * KNN + p]];
#pragma unroll
    for (int qq = 0; qq < 4; qq++) Q[qq] = g_pts_s[g_ni_after[nb * KNN + qq]];
#pragma unroll
    for (int p = 0; p < 4; p++)
#pragma unroll
        for (int qq = 0; qq < 4; qq++)
            o[12 + p * 4 + qq] = d_ref(P[p], Q[qq]);
}

// ---------------- adf: (S,28) = [intra_before(6) | intra_after(6) | inter(16)] ----------------
__global__ void adf_kernel(const int* __restrict__ si) {
    int s = blockIdx.x * blockDim.x + threadIdx.x;
    if (s >= S_PTS) return;
    float* o = g_adf + s * 28;
#pragma unroll
    for (int c = 0; c < 6; c++) o[c]     = g_intra_before[s * 6 + c];
#pragma unroll
    for (int c = 0; c < 6; c++) o[6 + c] = g_intra_after[s * 6 + c];
    float4 P[4], Q[4];
#pragma unroll
    for (int p = 0; p < 4; p++) P[p] = g_pts[g_ai_before[s * 4 + p]];
#pragma unroll
    for (int qq = 0; qq < 4; qq++) Q[qq] = g_pts[si[g_ni_after[s * KNN + qq]]];
#pragma unroll
    for (int p = 0; p < 4; p++)
#pragma unroll
        for (int qq = 0; qq < 4; qq++)
            o[12 + p * 4 + qq] = d_ref(P[p], Q[qq]);
}

// ---------------- GEMM1: y = adf @ W + b for Ww and Wb ----------------
__global__ void gemm1_kernel(const float* __restrict__ Ww, const float* __restrict__ bw,
                             const float* __restrict__ Wb, const float* __restrict__ bb) {
    int tid = blockIdx.x * blockDim.x + threadIdx.x;
    int ch = tid & 63, s = tid >> 6;
    if (s >= S_PTS) return;
    float aw = bw[ch], ab = bb[ch];
    const float* a = g_adf + s * 28;
#pragma unroll
    for (int c = 0; c < 28; c++) {
        float av = a[c];
        aw = fmaf(av, Ww[c * 64 + ch], aw);
        ab = fmaf(av, Wb[c * 64 + ch], ab);
    }
    g_yw[s * 64 + ch] = aw;
    g_yb[s * 64 + ch] = ab;
}

// ---------------- BN stats for yw/yb: one block per (matrix,channel) ----------------
__global__ void reduce1_kernel() {
    int b = blockIdx.x;                 // 0..127
    const float* y = (b < 64) ? g_yw : g_yb;
    int ch = b & 63;
    float s = 0.0f, s2 = 0.0f;
    for (int r = threadIdx.x; r < S_PTS; r += 256) {
        float v = y[r * 64 + ch];
        s += v; s2 = fmaf(v, v, s2);
    }
    __shared__ float sh[256], sh2[256];
    sh[threadIdx.x] = s; sh2[threadIdx.x] = s2;
    __syncthreads();
    for (int st = 128; st > 0; st >>= 1) {
        if (threadIdx.x < st) { sh[threadIdx.x] += sh[threadIdx.x + st]; sh2[threadIdx.x] += sh2[threadIdx.x + st]; }
        __syncthreads();
    }
    if (threadIdx.x == 0) {
        float mu  = sh[0] / (float)S_PTS;
        float var = sh2[0] / (float)S_PTS - mu * mu;
        float rs  = rsqrtf(var + 1e-5f);
        if (b < 64) { g_stats1[ch] = mu;       g_stats1[64 + ch] = rs; }
        else        { g_stats1[128 + ch] = mu; g_stats1[192 + ch] = rs; }
    }
}

// ---------------- pointwise1: BN affine + feature gate + leaky ----------------
__global__ void pw1_kernel(const float* __restrict__ feature, const int* __restrict__ si,
                           const float* __restrict__ gw, const float* __restrict__ betaw,
                           const float* __restrict__ gb, const float* __restrict__ betab) {
    int tid = blockIdx.x * blockDim.x + threadIdx.x;
    int ch = tid & 63, s = tid >> 6;
    if (s >= S_PTS) return;
    float w = (g_yw[tid] - g_stats1[ch])       * g_stats1[64 + ch]  * gw[ch] + betaw[ch];
    float b = (g_yb[tid] - g_stats1[128 + ch]) * g_stats1[192 + ch] * gb[ch] + betab[ch];
    float f = feature[si[s] * 64 + ch];
    g_fm[tid] = leaky(fmaf(f, w, b));
}

// ---------------- GEMM2: z = [fm | adf] @ Wo + bo ----------------
__global__ void gemm2_kernel(const float* __restrict__ Wo, const float* __restrict__ bo) {
    int tid = blockIdx.x * blockDim.x + threadIdx.x;
    int ch = tid & 127, s = tid >> 7;
    if (s >= S_PTS) return;
    float acc = bo[ch];
    const float* fm = g_fm + s * 64;
#pragma unroll
    for (int c = 0; c < 64; c++) acc = fmaf(fm[c], Wo[c * 128 + ch], acc);
    const float* a = g_adf + s * 28;
#pragma unroll
    for (int c = 0; c < 28; c++) acc = fmaf(a[c], Wo[(64 + c) * 128 + ch], acc);
    g_z[s * 128 + ch] = acc;
}

// ---------------- BN stats for z ----------------
__global__ void reduce2_kernel() {
    int ch = blockIdx.x;                // 0..127
    float s = 0.0f, s2 = 0.0f;
    for (int r = threadIdx.x; r < S_PTS; r += 256) {
        float v = g_z[r * 128 + ch];
        s += v; s2 = fmaf(v, v, s2);
    }
    __shared__ float sh[256], sh2[256];
    sh[threadIdx.x] = s; sh2[threadIdx.x] = s2;
    __syncthreads();
    for (int st = 128; st > 0; st >>= 1) {
        if (threadIdx.x < st) { sh[threadIdx.x] += sh[threadIdx.x + st]; sh2[threadIdx.x] += sh2[threadIdx.x + st]; }
        __syncthreads();
    }
    if (threadIdx.x == 0) {
        float mu  = sh[0] / (float)S_PTS;
        float var = sh2[0] / (float)S_PTS - mu * mu;
        g_stats2[ch]       = mu;
        g_stats2[128 + ch] = rsqrtf(var + 1e-5f);
    }
}

// ---------------- pointwise2: BN affine + leaky -> out feat ----------------
__global__ void pw2_kernel(const float* __restrict__ go, const float* __restrict__ betao,
                           float* __restrict__ out_feat) {
    int tid = blockIdx.x * blockDim.x + threadIdx.x;
    int ch = tid & 127, s = tid >> 7;
    if (s >= S_PTS) return;
    float v = (g_z[tid] - g_stats2[ch]) * g_stats2[128 + ch] * go[ch] + betao[ch];
    out_feat[tid] = leaky(v);
}

// ---------------- launch ----------------
extern "C" void kernel_launch(void* const* d_in, const int* in_sizes, int n_in,
                              void* d_out, int out_size) {
    const float* xyz     = (const float*)d_in[0];
    const float* feature = (const float*)d_in[1];
    const int*   si      = (const int*)  d_in[2];
    const float* Ww    = (const float*)d_in[3];
    const float* bw    = (const float*)d_in[4];
    const float* gw    = (const float*)d_in[5];
    const float* betaw = (const float*)d_in[6];
    const float* Wb    = (const float*)d_in[7];
    const float* bb    = (const float*)d_in[8];
    const float* gb    = (const float*)d_in[9];
    const float* betab = (const float*)d_in[10];
    const float* Wo    = (const float*)d_in[11];
    const float* bo    = (const float*)d_in[12];
    const float* go    = (const float*)d_in[13];
    const float* betao = (const float*)d_in[14];

    float* out        = (float*)d_out;
    float* out_xyz_s  = out;                                  // 4096*3
    float* out_feat   = out + S_PTS * 3;                      // 4096*128
    float* out_rf     = out_feat + S_PTS * 128;               // 4096*16*28
    float* out_ni     = out_rf + (size_t)S_PTS * KNN * 28;    // 4096*16

    prep_kernel<<<(N_PTS + 255) / 256, 256>>>(xyz, si, out_xyz_s);

    knn_kernel<4,  N_PTS, false><<<S_PTS / 256, 256>>>(nullptr);
    knn_kernel<16, S_PTS, true ><<<S_PTS / 256, 256>>>(out_ni);

    rf_kernel<<<(S_PTS * KNN) / 256, 256>>>(out_rf);
    adf_kernel<<<S_PTS / 256, 256>>>(si);

    gemm1_kernel<<<(S_PTS * 64) / 256, 256>>>(Ww, bw, Wb, bb);
    reduce1_kernel<<<128, 256>>>();
    pw1_kernel<<<(S_PTS * 64) / 256, 256>>>(feature, si, gw, betaw, gb, betab);

    gemm2_kernel<<<(S_PTS * 128) / 256, 256>>>(Wo, bo);
    reduce2_kernel<<<128, 256>>>();
    pw2_kernel<<<(S_PTS * 128) / 256, 256>>>(go, betao, out_feat);
}

// round 5
// speedup vs baseline: 3.5743x; 3.5743x over previous
#include <cuda_runtime.h>
#include <math.h>

#define N_PTS 8192
#define S_PTS 4096
#define KNN   16
#define CHUNK 512
#define CB    16        // before chunks: 16*512 = 8192
#define CA    8         // after chunks:   8*512 = 4096
#define QG    16        // query groups of 256 -> 4096

// ---------------- scratch (__device__ globals; no allocation allowed) ----------------
__device__ float4 g_pts[N_PTS];          // x,y,z,sq original points
__device__ float4 g_pts_s[S_PTS];        // x,y,z,sq sampled points
__device__ float  g_pb_d[CB * S_PTS * 4];
__device__ int    g_pb_i[CB * S_PTS * 4];
__device__ float  g_pa_d[CA * S_PTS * KNN];
__device__ int    g_pa_i[CA * S_PTS * KNN];
__device__ int    g_ni_after[S_PTS * KNN];
__device__ int4   g_anch_a[S_PTS];       // first 4 after-neighbors
__device__ int4   g_anch_b[S_PTS];       // first 4 before-neighbors (global idx)
__device__ float  g_intra_a8[S_PTS * 8]; // 6 intra dists, padded to 8
__device__ float  g_intra_b8[S_PTS * 8];
__device__ float  g_adf[S_PTS * 28];
__device__ float  g_yw[S_PTS * 64];
__device__ float  g_yb[S_PTS * 64];
__device__ float  g_fm[S_PTS * 64];
__device__ float  g_z[S_PTS * 128];
__device__ float  g_stats1[4 * 64];      // mu_w | rs_w | mu_b | rs_b
__device__ float  g_stats2[2 * 128];     // mu_o | rs_o

// ---------------- reference-rounding helpers ----------------
// sq: XLA reduce ((x^2 + y^2) + z^2), rn each op, no contraction
__device__ __forceinline__ float sq_ref(float x, float y, float z) {
    return __fadd_rn(__fadd_rn(__fmul_rn(x, x), __fmul_rn(y, y)), __fmul_rn(z, z));
}
// dot: cuBLAS SGEMM K=3 fma chain, acc0 = rn(x*x'); d2: rn elementwise fusion
__device__ __forceinline__ float d2_ref(float4 a, float4 b) {
    float dot = fmaf(a.z, b.z, fmaf(a.y, b.y, __fmul_rn(a.x, b.x)));
    float d2  = __fsub_rn(__fadd_rn(a.w, b.w), __fmul_rn(2.0f, dot));
    return fmaxf(d2, 0.0f);
}
__device__ __forceinline__ float d_ref(float4 a, float4 b) {
    float d2 = d2_ref(a, b);
    return d2 > 0.0f ? __fsqrt_rn(d2) : 0.0f;
}
__device__ __forceinline__ float leaky(float v) {
    return v >= 0.0f ? v : 0.2f * v;
}

// ---------------- prep ----------------
__global__ void prep_kernel(const float* __restrict__ xyz,
                            const int* __restrict__ si,
                            float* __restrict__ out_xyz_s) {
    int i = blockIdx.x * blockDim.x + threadIdx.x;
    if (i < N_PTS) {
        float x = xyz[3 * i], y = xyz[3 * i + 1], z = xyz[3 * i + 2];
        g_pts[i] = make_float4(x, y, z, sq_ref(x, y, z));
    }
    if (i < S_PTS) {
        int g = si[i];
        float x = xyz[3 * g], y = xyz[3 * g + 1], z = xyz[3 * g + 2];
        g_pts_s[i] = make_float4(x, y, z, sq_ref(x, y, z));
        out_xyz_s[3 * i]     = x;
        out_xyz_s[3 * i + 1] = y;
        out_xyz_s[3 * i + 2] = z;
    }
}

// ---------------- chunk scan: per-thread top-K of one 512-candidate chunk ----------------
// Scan order ascending index; strict-< insert => tie -> lower index. Exact d domain
// on prefilter survivors (fma prefilter margin 1e-3 >> rounding gap ~1e-5 abs).
template <int K>
__device__ __forceinline__ void scan_chunk(const float4* __restrict__ tile, int base,
                                           float4 qp, float* __restrict__ out_d,
                                           int* __restrict__ out_i) {
    float ld[K]; int li[K];
#pragma unroll
    for (int r = 0; r < K; r++) { ld[r] = 3.4e38f; li[r] = 0x7fffffff; }
    float thrf = 3.4e38f;
#pragma unroll 4
    for (int t = 0; t < CHUNK; t++) {
        float4 cp = tile[t];
        float dotf = fmaf(qp.z, cp.z, fmaf(qp.y, cp.y, qp.x * cp.x));
        float d2f  = fmaf(-2.0f, dotf, qp.w + cp.w);
        if (d2f < thrf) {
            float d = d_ref(qp, cp);
            if (d < ld[K - 1]) {
                float v = d; int vi = base + t;
#pragma unroll
                for (int r = 0; r < K; r++) {
                    if (v < ld[r]) {
                        float tv = ld[r]; ld[r] = v; v = tv;
                        int   ti = li[r]; li[r] = vi; vi = ti;
                    }
                }
                thrf = fmaf(ld[K - 1], ld[K - 1], 1e-3f);
            }
        }
    }
#pragma unroll
    for (int r = 0; r < K; r += 4) {
        *(float4*)(out_d + r) = make_float4(ld[r], ld[r + 1], ld[r + 2], ld[r + 3]);
        *(int4*)  (out_i + r) = make_int4(li[r], li[r + 1], li[r + 2], li[r + 3]);
    }
}

// ---------------- fused partial-KNN: 256 before-blocks + 128 after-blocks ----------------
__global__ void __launch_bounds__(256) knn_partial_kernel() {
    __shared__ float4 tile[CHUNK];
    int b = blockIdx.x;
    if (b < QG * CB) {
        int qg = b >> 4, ck = b & 15;
        int base = ck * CHUNK;
        for (int t = threadIdx.x; t < CHUNK; t += 256) tile[t] = g_pts[base + t];
        __syncthreads();
        int q = qg * 256 + threadIdx.x;
        scan_chunk<4>(tile, base, g_pts_s[q],
                      g_pb_d + ((size_t)ck * S_PTS + q) * 4,
                      g_pb_i + ((size_t)ck * S_PTS + q) * 4);
    } else {
        int b2 = b - QG * CB;
        int qg = b2 >> 3, ck = b2 & 7;
        int base = ck * CHUNK;
        for (int t = threadIdx.x; t < CHUNK; t += 256) tile[t] = g_pts_s[base + t];
        __syncthreads();
        int q = qg * 256 + threadIdx.x;
        scan_chunk<16>(tile, base, g_pts_s[q],
                       g_pa_d + ((size_t)ck * S_PTS + q) * KNN,
                       g_pa_i + ((size_t)ck * S_PTS + q) * KNN);
    }
}

// lexicographic (d, idx) insert into sorted list (exact global top-K tie rule)
template <int K>
__device__ __forceinline__ void insert_lex(float v, int vi, float (&ld)[K], int (&li)[K]) {
    if (v < ld[K - 1] || (v == ld[K - 1] && vi < li[K - 1])) {
#pragma unroll
        for (int r = 0; r < K; r++) {
            bool lt = (v < ld[r]) || (v == ld[r] && vi < li[r]);
            if (lt) {
                float tv = ld[r]; ld[r] = v; v = tv;
                int   ti = li[r]; li[r] = vi; vi = ti;
            }
        }
    }
}

__device__ __forceinline__ void write_intra8(float* dst, float d1, float d2, float d3,
                                             float4 A1, float4 A2, float4 A3) {
    *(float4*)dst       = make_float4(d1, d2, d3, d_ref(A1, A2));
    *(float4*)(dst + 4) = make_float4(d_ref(A1, A3), d_ref(A2, A3), 0.0f, 0.0f);
}

// ---------------- merge: 16 before-blocks + 16 after-blocks, thread per query ----------------
__global__ void __launch_bounds__(256) knn_merge_kernel(float* __restrict__ out_ni_f) {
    int b = blockIdx.x;
    if (b < 16) {                                  // BEFORE merge: K=4 over 16 chunks
        int q = b * 256 + threadIdx.x;
        float ld[4]; int li[4];
#pragma unroll
        for (int r = 0; r < 4; r++) { ld[r] = 3.4e38f; li[r] = 0x7fffffff; }
        for (int c = 0; c < CB; c++) {
            float4 dv = *(const float4*)(g_pb_d + ((size_t)c * S_PTS + q) * 4);
            if (dv.x > ld[3]) continue;
            int4 iv = *(const int4*)(g_pb_i + ((size_t)c * S_PTS + q) * 4);
            insert_lex<4>(dv.x, iv.x, ld, li);
            insert_lex<4>(dv.y, iv.y, ld, li);
            insert_lex<4>(dv.z, iv.z, ld, li);
            insert_lex<4>(dv.w, iv.w, ld, li);
        }
        g_anch_b[q] = make_int4(li[0], li[1], li[2], li[3]);
        write_intra8(g_intra_b8 + q * 8, ld[1], ld[2], ld[3],
                     g_pts[li[1]], g_pts[li[2]], g_pts[li[3]]);
    } else {                                       // AFTER merge: K=16 over 8 chunks
        int q = (b - 16) * 256 + threadIdx.x;
        float ld[16]; int li[16];
#pragma unroll
        for (int r = 0; r < 16; r++) { ld[r] = 3.4e38f; li[r] = 0x7fffffff; }
        for (int c = 0; c < CA; c++) {
            const float* pd = g_pa_d + ((size_t)c * S_PTS + q) * KNN;
            const int*   pi = g_pa_i + ((size_t)c * S_PTS + q) * KNN;
#pragma unroll
            for (int r4 = 0; r4 < 16; r4 += 4) {
                float4 dv = *(const float4*)(pd + r4);
                if (dv.x > ld[15]) break;
                int4 iv = *(const int4*)(pi + r4);
                insert_lex<16>(dv.x, iv.x, ld, li);
                insert_lex<16>(dv.y, iv.y, ld, li);
                insert_lex<16>(dv.z, iv.z, ld, li);
                insert_lex<16>(dv.w, iv.w, ld, li);
            }
        }
#pragma unroll
        for (int r = 0; r < 16; r += 4) {
            *(int4*)(g_ni_after + q * KNN + r) = make_int4(li[r], li[r+1], li[r+2], li[r+3]);
            *(float4*)(out_ni_f + q * KNN + r) =
                make_float4((float)li[r], (float)li[r+1], (float)li[r+2], (float)li[r+3]);
        }
        g_anch_a[q] = make_int4(li[0], li[1], li[2], li[3]);
        write_intra8(g_intra_a8 + q * 8, ld[1], ld[2], ld[3],
                     g_pts_s[li[1]], g_pts_s[li[2]], g_pts_s[li[3]]);
    }
}

// ---------------- fused rf (256 blocks) + adf (16 blocks) ----------------
__global__ void __launch_bounds__(256) rf_adf_kernel(float* __restrict__ out_rf,
                                                     const int* __restrict__ si) {
    int b = blockIdx.x;
    if (b < 256) {
        int i = b * 256 + threadIdx.x;            // < 65536
        int n = i >> 4, k = i & 15;
        int nb = g_ni_after[n * KNN + k];
        float4 a0 = *(const float4*)(g_intra_a8 + n * 8);
        float4 a1 = *(const float4*)(g_intra_a8 + n * 8 + 4);
        float4 c0 = *(const float4*)(g_intra_a8 + nb * 8);
        float4 c1 = *(const float4*)(g_intra_a8 + nb * 8 + 4);
        int4 an  = g_anch_a[n];
        int4 anb = g_anch_a[nb];
        float4 P0 = g_pts_s[an.x],  P1 = g_pts_s[an.y],  P2 = g_pts_s[an.z],  P3 = g_pts_s[an.w];
        float4 Q0 = g_pts_s[anb.x], Q1 = g_pts_s[anb.y], Q2 = g_pts_s[anb.z], Q3 = g_pts_s[anb.w];
        float* o = out_rf + (size_t)i * 28;
        ((float4*)o)[0] = make_float4(a0.x, a0.y, a0.z, a0.w);
        ((float4*)o)[1] = make_float4(a1.x, a1.y, c0.x, c0.y);
        ((float4*)o)[2] = make_float4(c0.z, c0.w, c1.x, c1.y);
        ((float4*)o)[3] = make_float4(d_ref(P0,Q0), d_ref(P0,Q1), d_ref(P0,Q2), d_ref(P0,Q3));
        ((float4*)o)[4] = make_float4(d_ref(P1,Q0), d_ref(P1,Q1), d_ref(P1,Q2), d_ref(P1,Q3));
        ((float4*)o)[5] = make_float4(d_ref(P2,Q0), d_ref(P2,Q1), d_ref(P2,Q2), d_ref(P2,Q3));
        ((float4*)o)[6] = make_float4(d_ref(P3,Q0), d_ref(P3,Q1), d_ref(P3,Q2), d_ref(P3,Q3));
    } else {
        int s = (b - 256) * 256 + threadIdx.x;    // < 4096
        float4 b0 = *(const float4*)(g_intra_b8 + s * 8);
        float4 b1 = *(const float4*)(g_intra_b8 + s * 8 + 4);
        float4 a0 = *(const float4*)(g_intra_a8 + s * 8);
        float4 a1 = *(const float4*)(g_intra_a8 + s * 8 + 4);
        int4 ab = g_anch_b[s];
        int4 aa = g_anch_a[s];
        float4 P0 = g_pts[ab.x], P1 = g_pts[ab.y], P2 = g_pts[ab.z], P3 = g_pts[ab.w];
        float4 Q0 = g_pts[si[aa.x]], Q1 = g_pts[si[aa.y]], Q2 = g_pts[si[aa.z]], Q3 = g_pts[si[aa.w]];
        float* o = g_adf + s * 28;
        ((float4*)o)[0] = make_float4(b0.x, b0.y, b0.z, b0.w);
        ((float4*)o)[1] = make_float4(b1.x, b1.y, a0.x, a0.y);
        ((float4*)o)[2] = make_float4(a0.z, a0.w, a1.x, a1.y);
        ((float4*)o)[3] = make_float4(d_ref(P0,Q0), d_ref(P0,Q1), d_ref(P0,Q2), d_ref(P0,Q3));
        ((float4*)o)[4] = make_float4(d_ref(P1,Q0), d_ref(P1,Q1), d_ref(P1,Q2), d_ref(P1,Q3));
        ((float4*)o)[5] = make_float4(d_ref(P2,Q0), d_ref(P2,Q1), d_ref(P2,Q2), d_ref(P2,Q3));
        ((float4*)o)[6] = make_float4(d_ref(P3,Q0), d_ref(P3,Q1), d_ref(P3,Q2), d_ref(P3,Q3));
    }
}

// ---------------- GEMM1: y = adf @ W + b for Ww and Wb ----------------
__global__ void gemm1_kernel(const float* __restrict__ Ww, const float* __restrict__ bw,
                             const float* __restrict__ Wb, const float* __restrict__ bb) {
    int tid = blockIdx.x * blockDim.x + threadIdx.x;
    int ch = tid & 63, s = tid >> 6;
    if (s >= S_PTS) return;
    float aw = bw[ch], ab = bb[ch];
    const float* a = g_adf + s * 28;
#pragma unroll
    for (int c = 0; c < 28; c++) {
        float av = a[c];
        aw = fmaf(av, Ww[c * 64 + ch], aw);
        ab = fmaf(av, Wb[c * 64 + ch], ab);
    }
    g_yw[s * 64 + ch] = aw;
    g_yb[s * 64 + ch] = ab;
}

// ---------------- BN stats for yw/yb ----------------
__global__ void reduce1_kernel() {
    int b = blockIdx.x;                 // 0..127
    const float* y = (b < 64) ? g_yw : g_yb;
    int ch = b & 63;
    float s = 0.0f, s2 = 0.0f;
    for (int r = threadIdx.x; r < S_PTS; r += 256) {
        float v = y[r * 64 + ch];
        s += v; s2 = fmaf(v, v, s2);
    }
    __shared__ float sh[256], sh2[256];
    sh[threadIdx.x] = s; sh2[threadIdx.x] = s2;
    __syncthreads();
    for (int st = 128; st > 0; st >>= 1) {
        if (threadIdx.x < st) { sh[threadIdx.x] += sh[threadIdx.x + st]; sh2[threadIdx.x] += sh2[threadIdx.x + st]; }
        __syncthreads();
    }
    if (threadIdx.x == 0) {
        float mu  = sh[0] / (float)S_PTS;
        float var = sh2[0] / (float)S_PTS - mu * mu;
        float rs  = rsqrtf(var + 1e-5f);
        if (b < 64) { g_stats1[ch] = mu;       g_stats1[64 + ch] = rs; }
        else        { g_stats1[128 + ch] = mu; g_stats1[192 + ch] = rs; }
    }
}

// ---------------- pointwise1 ----------------
__global__ void pw1_kernel(const float* __restrict__ feature, const int* __restrict__ si,
                           const float* __restrict__ gw, const float* __restrict__ betaw,
                           const float* __restrict__ gb, const float* __restrict__ betab) {
    int tid = blockIdx.x * blockDim.x + threadIdx.x;
    int ch = tid & 63, s = tid >> 6;
    if (s >= S_PTS) return;
    float w = (g_yw[tid] - g_stats1[ch])       * g_stats1[64 + ch]  * gw[ch] + betaw[ch];
    float b = (g_yb[tid] - g_stats1[128 + ch]) * g_stats1[192 + ch] * gb[ch] + betab[ch];
    float f = feature[si[s] * 64 + ch];
    g_fm[tid] = leaky(fmaf(f, w, b));
}

// ---------------- GEMM2 ----------------
__global__ void gemm2_kernel(const float* __restrict__ Wo, const float* __restrict__ bo) {
    int tid = blockIdx.x * blockDim.x + threadIdx.x;
    int ch = tid & 127, s = tid >> 7;
    if (s >= S_PTS) return;
    float acc = bo[ch];
    const float* fm = g_fm + s * 64;
#pragma unroll
    for (int c = 0; c < 64; c++) acc = fmaf(fm[c], Wo[c * 128 + ch], acc);
    const float* a = g_adf + s * 28;
#pragma unroll
    for (int c = 0; c < 28; c++) acc = fmaf(a[c], Wo[(64 + c) * 128 + ch], acc);
    g_z[s * 128 + ch] = acc;
}

// ---------------- BN stats for z ----------------
__global__ void reduce2_kernel() {
    int ch = blockIdx.x;                // 0..127
    float s = 0.0f, s2 = 0.0f;
    for (int r = threadIdx.x; r < S_PTS; r += 256) {
        float v = g_z[r * 128 + ch];
        s += v; s2 = fmaf(v, v, s2);
    }
    __shared__ float sh[256], sh2[256];
    sh[threadIdx.x] = s; sh2[threadIdx.x] = s2;
    __syncthreads();
    for (int st = 128; st > 0; st >>= 1) {
        if (threadIdx.x < st) { sh[threadIdx.x] += sh[threadIdx.x + st]; sh2[threadIdx.x] += sh2[threadIdx.x + st]; }
        __syncthreads();
    }
    if (threadIdx.x == 0) {
        float mu  = sh[0] / (float)S_PTS;
        float var = sh2[0] / (float)S_PTS - mu * mu;
        g_stats2[ch]       = mu;
        g_stats2[128 + ch] = rsqrtf(var + 1e-5f);
    }
}

// ---------------- pointwise2 ----------------
__global__ void pw2_kernel(const float* __restrict__ go, const float* __restrict__ betao,
                           float* __restrict__ out_feat) {
    int tid = blockIdx.x * blockDim.x + threadIdx.x;
    int ch = tid & 127, s = tid >> 7;
    if (s >= S_PTS) return;
    float v = (g_z[tid] - g_stats2[ch]) * g_stats2[128 + ch] * go[ch] + betao[ch];
    out_feat[tid] = leaky(v);
}

// ---------------- launch ----------------
extern "C" void kernel_launch(void* const* d_in, const int* in_sizes, int n_in,
                              void* d_out, int out_size) {
    const float* xyz     = (const float*)d_in[0];
    const float* feature = (const float*)d_in[1];
    const int*   si      = (const int*)  d_in[2];
    const float* Ww    = (const float*)d_in[3];
    const float* bw    = (const float*)d_in[4];
    const float* gw    = (const float*)d_in[5];
    const float* betaw = (const float*)d_in[6];
    const float* Wb    = (const float*)d_in[7];
    const float* bb    = (const float*)d_in[8];
    const float* gb    = (const float*)d_in[9];
    const float* betab = (const float*)d_in[10];
    const float* Wo    = (const float*)d_in[11];
    const float* bo    = (const float*)d_in[12];
    const float* go    = (const float*)d_in[13];
    const float* betao = (const float*)d_in[14];

    float* out        = (float*)d_out;
    float* out_xyz_s  = out;                                  // 4096*3
    float* out_feat   = out + S_PTS * 3;                      // 4096*128
    float* out_rf     = out_feat + S_PTS * 128;               // 4096*16*28
    float* out_ni     = out_rf + (size_t)S_PTS * KNN * 28;    // 4096*16

    prep_kernel<<<(N_PTS + 255) / 256, 256>>>(xyz, si, out_xyz_s);

    knn_partial_kernel<<<QG * CB + QG * CA, 256>>>();          // 384 blocks
    knn_merge_kernel<<<32, 256>>>(out_ni);

    rf_adf_kernel<<<272, 256>>>(out_rf, si);

    gemm1_kernel<<<(S_PTS * 64) / 256, 256>>>(Ww, bw, Wb, bb);
    reduce1_kernel<<<128, 256>>>();
    pw1_kernel<<<(S_PTS * 64) / 256, 256>>>(feature, si, gw, betaw, gb, betab);

    gemm2_kernel<<<(S_PTS * 128) / 256, 256>>>(Wo, bo);
    reduce2_kernel<<<128, 256>>>();
    pw2_kernel<<<(S_PTS * 128) / 256, 256>>>(go, betao, out_feat);
}

// round 6
// speedup vs baseline: 6.9095x; 1.9331x over previous
#include <cuda_runtime.h>
#include <math.h>

#define N_PTS 8192
#define S_PTS 4096
#define KNN   16
#define FULLM 0xffffffffu

// ---------------- scratch (__device__ globals; no allocation allowed) ----------------
__device__ float4 g_pts[N_PTS];          // x,y,z,sq original points
__device__ float4 g_pts_s[S_PTS];        // x,y,z,sq sampled points
__device__ int    g_ni_after[S_PTS * KNN];
__device__ int4   g_anch_a[S_PTS];       // first 4 after-neighbors (sampled idx)
__device__ int4   g_anch_b[S_PTS];       // first 4 before-neighbors (global idx)
__device__ float  g_intra_a8[S_PTS * 8]; // 6 intra dists, padded to 8
__device__ float  g_intra_b8[S_PTS * 8];
__device__ float  g_adf[S_PTS * 28];
__device__ float  g_fm[S_PTS * 64];
__device__ float  g_z[S_PTS * 128];

// ---------------- reference-rounding helpers ----------------
__device__ __forceinline__ float sq_ref(float x, float y, float z) {
    return __fadd_rn(__fadd_rn(__fmul_rn(x, x), __fmul_rn(y, y)), __fmul_rn(z, z));
}
// dot: cuBLAS SGEMM K=3 fma chain, acc0 = rn(x*x'); d2: rn elementwise fusion
__device__ __forceinline__ float d2_ref(float4 a, float4 b) {
    float dot = fmaf(a.z, b.z, fmaf(a.y, b.y, __fmul_rn(a.x, b.x)));
    float d2  = __fsub_rn(__fadd_rn(a.w, b.w), __fmul_rn(2.0f, dot));
    return fmaxf(d2, 0.0f);
}
__device__ __forceinline__ float d_ref(float4 a, float4 b) {
    float d2 = d2_ref(a, b);
    return d2 > 0.0f ? __fsqrt_rn(d2) : 0.0f;
}
__device__ __forceinline__ float leaky(float v) {
    return v >= 0.0f ? v : 0.2f * v;
}
__device__ __forceinline__ unsigned long long kmin64(unsigned long long a, unsigned long long b) {
    return a < b ? a : b;
}
__device__ __forceinline__ unsigned long long kmax64(unsigned long long a, unsigned long long b) {
    return a > b ? a : b;
}

// ---------------- prep ----------------
__global__ void prep_kernel(const float* __restrict__ xyz,
                            const int* __restrict__ si,
                            float* __restrict__ out_xyz_s) {
    int i = blockIdx.x * blockDim.x + threadIdx.x;
    if (i < N_PTS) {
        float x = xyz[3 * i], y = xyz[3 * i + 1], z = xyz[3 * i + 2];
        g_pts[i] = make_float4(x, y, z, sq_ref(x, y, z));
    }
    if (i < S_PTS) {
        int g = si[i];
        float x = xyz[3 * g], y = xyz[3 * g + 1], z = xyz[3 * g + 2];
        g_pts_s[i] = make_float4(x, y, z, sq_ref(x, y, z));
        out_xyz_s[3 * i]     = x;
        out_xyz_s[3 * i + 1] = y;
        out_xyz_s[3 * i + 2] = z;
    }
}

// ---------------- KNN: warp-per-query, lane-distributed sorted top-K ----------------
// key = (f32bits(d) << 13) | idx  : integer order == lex (d, idx), tie -> lower index,
// exactly jax.lax.top_k(-D) semantics (d >= 0 so float bits are monotone).
// List lives one element per lane (lanes 0..K-1). Inserts are warp-collective:
// ballot -> position, shfl_up shift — no divergence union, ~8 instr.
template <int K, int NC, bool AFTER>
__device__ __forceinline__ void knn_warp(int q, int lane, float* __restrict__ out_ni_f) {
    const float4* __restrict__ cand = AFTER ? g_pts_s : g_pts;
    float4 qp = g_pts_s[q];

    // init: exact keys for first 32 candidates, bitonic sort ascending across lanes
    float4 c0 = cand[lane];
    float d0 = d_ref(qp, c0);
    unsigned long long key = ((unsigned long long)__float_as_uint(d0) << 13) | (unsigned)lane;
#pragma unroll
    for (int k = 2; k <= 32; k <<= 1) {
#pragma unroll
        for (int j = k >> 1; j > 0; j >>= 1) {
            unsigned long long other = __shfl_xor_sync(FULLM, key, j);
            bool takemin = (((lane & k) == 0) == ((lane & j) == 0));
            key = takemin ? kmin64(key, other) : kmax64(key, other);
        }
    }
    // ranks >= K of the first 32 are dominated by ranks 0..K-1 -> can never be in top-K
    if (lane >= K) key = ~0ull;

    unsigned long long kth = __shfl_sync(FULLM, key, K - 1);
    float dk = __uint_as_float((unsigned)(kth >> 13));
    float thrf = fmaf(dk, dk, 1e-3f);   // conservative superset of (d <= d_K) in fma domain

    for (int t = 32; t < NC; t += 32) {
        float4 cp = cand[t + lane];
        float dotf = fmaf(qp.z, cp.z, fmaf(qp.y, cp.y, qp.x * cp.x));
        float d2f  = fmaf(-2.0f, dotf, qp.w + cp.w);
        bool surv = d2f < thrf;
        unsigned long long nk = ~0ull;
        if (surv) {
            float de = d_ref(qp, cp);   // exact reference arithmetic
            nk = ((unsigned long long)__float_as_uint(de) << 13) | (unsigned)(t + lane);
        }
        unsigned bal = __ballot_sync(FULLM, surv);
        while (bal) {                              // ascending lane = ascending idx
            int pl = __ffs(bal) - 1;
            bal &= bal - 1;
            unsigned long long ck = __shfl_sync(FULLM, nk, pl);
            unsigned lt = __ballot_sync(FULLM, ck < key);
            int pos = __ffs(lt) - 1;               // uniform across warp
            if (pos < K) {
                unsigned long long up = __shfl_up_sync(FULLM, key, 1);
                if (lane == pos)      key = ck;
                else if (lane > pos)  key = up;
                if (lane >= K)        key = ~0ull;
            }
        }
        kth  = __shfl_sync(FULLM, key, K - 1);
        dk   = __uint_as_float((unsigned)(kth >> 13));
        thrf = fmaf(dk, dk, 1e-3f);
    }

    int idx = (int)(key & 0x1FFFu);
    if (AFTER && lane < K) {
        g_ni_after[q * KNN + lane] = idx;
        out_ni_f[q * KNN + lane]   = (float)idx;
    }
    unsigned long long k1 = __shfl_sync(FULLM, key, 1);
    unsigned long long k2 = __shfl_sync(FULLM, key, 2);
    unsigned long long k3 = __shfl_sync(FULLM, key, 3);
    if (lane == 0) {
        int i1 = (int)(k1 & 0x1FFF), i2 = (int)(k2 & 0x1FFF), i3 = (int)(k3 & 0x1FFF);
        float d1  = __uint_as_float((unsigned)(k1 >> 13));
        float d2v = __uint_as_float((unsigned)(k2 >> 13));
        float d3  = __uint_as_float((unsigned)(k3 >> 13));
        float4 A1 = cand[i1], A2 = cand[i2], A3 = cand[i3];
        float* intra = AFTER ? (g_intra_a8 + q * 8) : (g_intra_b8 + q * 8);
        *(float4*)intra       = make_float4(d1, d2v, d3, d_ref(A1, A2));
        *(float4*)(intra + 4) = make_float4(d_ref(A1, A3), d_ref(A2, A3), 0.0f, 0.0f);
        if (AFTER) g_anch_a[q] = make_int4(idx, i1, i2, i3);
        else       g_anch_b[q] = make_int4(idx, i1, i2, i3);
    }
}

__global__ void __launch_bounds__(256) knn_kernel(float* __restrict__ out_ni_f) {
    int gw   = blockIdx.x * 8 + (threadIdx.x >> 5);
    int lane = threadIdx.x & 31;
    if (gw < S_PTS) knn_warp<KNN, S_PTS, true >(gw, lane, out_ni_f);
    else            knn_warp<4,   N_PTS, false>(gw - S_PTS, lane, out_ni_f);
}

// ---------------- fused rf (256 blocks) + adf (16 blocks) ----------------
__global__ void __launch_bounds__(256) rf_adf_kernel(float* __restrict__ out_rf,
                                                     const int* __restrict__ si) {
    int b = blockIdx.x;
    if (b < 256) {
        int i = b * 256 + threadIdx.x;            // < 65536
        int n = i >> 4, k = i & 15;
        int nb = g_ni_after[n * KNN + k];
        float4 a0 = *(const float4*)(g_intra_a8 + n * 8);
        float4 a1 = *(const float4*)(g_intra_a8 + n * 8 + 4);
        float4 c0 = *(const float4*)(g_intra_a8 + nb * 8);
        float4 c1 = *(const float4*)(g_intra_a8 + nb * 8 + 4);
        int4 an  = g_anch_a[n];
        int4 anb = g_anch_a[nb];
        float4 P0 = g_pts_s[an.x],  P1 = g_pts_s[an.y],  P2 = g_pts_s[an.z],  P3 = g_pts_s[an.w];
        float4 Q0 = g_pts_s[anb.x], Q1 = g_pts_s[anb.y], Q2 = g_pts_s[anb.z], Q3 = g_pts_s[anb.w];
        float* o = out_rf + (size_t)i * 28;
        ((float4*)o)[0] = make_float4(a0.x, a0.y, a0.z, a0.w);
        ((float4*)o)[1] = make_float4(a1.x, a1.y, c0.x, c0.y);
        ((float4*)o)[2] = make_float4(c0.z, c0.w, c1.x, c1.y);
        ((float4*)o)[3] = make_float4(d_ref(P0,Q0), d_ref(P0,Q1), d_ref(P0,Q2), d_ref(P0,Q3));
        ((float4*)o)[4] = make_float4(d_ref(P1,Q0), d_ref(P1,Q1), d_ref(P1,Q2), d_ref(P1,Q3));
        ((float4*)o)[5] = make_float4(d_ref(P2,Q0), d_ref(P2,Q1), d_ref(P2,Q2), d_ref(P2,Q3));
        ((float4*)o)[6] = make_float4(d_ref(P3,Q0), d_ref(P3,Q1), d_ref(P3,Q2), d_ref(P3,Q3));
    } else {
        int s = (b - 256) * 256 + threadIdx.x;    // < 4096
        float4 b0 = *(const float4*)(g_intra_b8 + s * 8);
        float4 b1 = *(const float4*)(g_intra_b8 + s * 8 + 4);
        float4 a0 = *(const float4*)(g_intra_a8 + s * 8);
        float4 a1 = *(const float4*)(g_intra_a8 + s * 8 + 4);
        int4 ab = g_anch_b[s];
        int4 aa = g_anch_a[s];
        float4 P0 = g_pts[ab.x], P1 = g_pts[ab.y], P2 = g_pts[ab.z], P3 = g_pts[ab.w];
        float4 Q0 = g_pts[si[aa.x]], Q1 = g_pts[si[aa.y]], Q2 = g_pts[si[aa.z]], Q3 = g_pts[si[aa.w]];
        float* o = g_adf + s * 28;
        ((float4*)o)[0] = make_float4(b0.x, b0.y, b0.z, b0.w);
        ((float4*)o)[1] = make_float4(b1.x, b1.y, a0.x, a0.y);
        ((float4*)o)[2] = make_float4(a0.z, a0.w, a1.x, a1.y);
        ((float4*)o)[3] = make_float4(d_ref(P0,Q0), d_ref(P0,Q1), d_ref(P0,Q2), d_ref(P0,Q3));
        ((float4*)o)[4] = make_float4(d_ref(P1,Q0), d_ref(P1,Q1), d_ref(P1,Q2), d_ref(P1,Q3));
        ((float4*)o)[5] = make_float4(d_ref(P2,Q0), d_ref(P2,Q1), d_ref(P2,Q2), d_ref(P2,Q3));
        ((float4*)o)[6] = make_float4(d_ref(P3,Q0), d_ref(P3,Q1), d_ref(P3,Q2), d_ref(P3,Q3));
    }
}

// ---------------- mlp1: gemm1 + BN stats + pw1 fused, one block per channel ----------------
__global__ void __launch_bounds__(256) mlp1_kernel(
    const float* __restrict__ Ww, const float* __restrict__ bw,
    const float* __restrict__ gw, const float* __restrict__ betaw,
    const float* __restrict__ Wb, const float* __restrict__ bb,
    const float* __restrict__ gb, const float* __restrict__ betab,
    const float* __restrict__ feature, const int* __restrict__ si) {
    __shared__ float wws[28], wbs[28];
    __shared__ float ys[2 * 16 * 256];     // yw then yb
    __shared__ float red[256], red2[256];
    __shared__ float stats[4];
    int ch = blockIdx.x, tid = threadIdx.x;
    if (tid < 28) { wws[tid] = Ww[tid * 64 + ch]; wbs[tid] = Wb[tid * 64 + ch]; }
    __syncthreads();
    float bwv = bw[ch], bbv = bb[ch];
    float sw = 0.f, s2w = 0.f, sb = 0.f, s2b = 0.f;
#pragma unroll
    for (int i = 0; i < 16; i++) {
        int s = i * 256 + tid;
        const float* a = g_adf + s * 28;
        float vw = bwv, vb = bbv;
#pragma unroll
        for (int c = 0; c < 28; c++) {
            float av = a[c];
            vw = fmaf(av, wws[c], vw);
            vb = fmaf(av, wbs[c], vb);
        }
        ys[i * 256 + tid]            = vw;
        ys[4096 + i * 256 + tid]     = vb;
        sw += vw; s2w = fmaf(vw, vw, s2w);
        sb += vb; s2b = fmaf(vb, vb, s2b);
    }
    // stats for w
    red[tid] = sw; red2[tid] = s2w; __syncthreads();
    for (int st = 128; st > 0; st >>= 1) {
        if (tid < st) { red[tid] += red[tid + st]; red2[tid] += red2[tid + st]; }
        __syncthreads();
    }
    if (tid == 0) {
        float mu = red[0] / (float)S_PTS;
        float var = red2[0] / (float)S_PTS - mu * mu;
        stats[0] = mu; stats[1] = rsqrtf(var + 1e-5f);
    }
    __syncthreads();
    // stats for b
    red[tid] = sb; red2[tid] = s2b; __syncthreads();
    for (int st = 128; st > 0; st >>= 1) {
        if (tid < st) { red[tid] += red[tid + st]; red2[tid] += red2[tid + st]; }
        __syncthreads();
    }
    if (tid == 0) {
        float mu = red[0] / (float)S_PTS;
        float var = red2[0] / (float)S_PTS - mu * mu;
        stats[2] = mu; stats[3] = rsqrtf(var + 1e-5f);
    }
    __syncthreads();
    float muw = stats[0], rsw = stats[1], mub = stats[2], rsb = stats[3];
    float gwv = gw[ch], bew = betaw[ch], gbv = gb[ch], beb = betab[ch];
#pragma unroll
    for (int i = 0; i < 16; i++) {
        int s = i * 256 + tid;
        float w = (ys[i * 256 + tid] - muw) * rsw * gwv + bew;
        float b = (ys[4096 + i * 256 + tid] - mub) * rsb * gbv + beb;
        float f = feature[si[s] * 64 + ch];
        g_fm[s * 64 + ch] = leaky(fmaf(f, w, b));
    }
}

// ---------------- GEMM2: z = [fm | adf] @ Wo + bo ----------------
__global__ void gemm2_kernel(const float* __restrict__ Wo, const float* __restrict__ bo) {
    int tid = blockIdx.x * blockDim.x + threadIdx.x;
    int ch = tid & 127, s = tid >> 7;
    if (s >= S_PTS) return;
    float acc = bo[ch];
    const float* fm = g_fm + s * 64;
#pragma unroll
    for (int c = 0; c < 64; c++) acc = fmaf(fm[c], Wo[c * 128 + ch], acc);
    const float* a = g_adf + s * 28;
#pragma unroll
    for (int c = 0; c < 28; c++) acc = fmaf(a[c], Wo[(64 + c) * 128 + ch], acc);
    g_z[s * 128 + ch] = acc;
}

// ---------------- bnpw2: BN stats + affine + leaky fused, one block per channel ----------------
__global__ void __launch_bounds__(256) bnpw2_kernel(const float* __restrict__ go,
                                                    const float* __restrict__ betao,
                                                    float* __restrict__ out_feat) {
    int ch = blockIdx.x, tid = threadIdx.x;
    float s = 0.0f, s2 = 0.0f;
    for (int r = tid; r < S_PTS; r += 256) {
        float v = g_z[r * 128 + ch];
        s += v; s2 = fmaf(v, v, s2);
    }
    __shared__ float sh[256], sh2[256];
    __shared__ float stats[2];
    sh[tid] = s; sh2[tid] = s2;
    __syncthreads();
    for (int st = 128; st > 0; st >>= 1) {
        if (tid < st) { sh[tid] += sh[tid + st]; sh2[tid] += sh2[tid + st]; }
        __syncthreads();
    }
    if (tid == 0) {
        float mu = sh[0] / (float)S_PTS;
        float var = sh2[0] / (float)S_PTS - mu * mu;
        stats[0] = mu; stats[1] = rsqrtf(var + 1e-5f);
    }
    __syncthreads();
    float mu = stats[0], rs = stats[1], gv = go[ch], be = betao[ch];
    for (int r = tid; r < S_PTS; r += 256) {
        float v = (g_z[r * 128 + ch] - mu) * rs * gv + be;
        out_feat[r * 128 + ch] = leaky(v);
    }
}

// ---------------- launch ----------------
extern "C" void kernel_launch(void* const* d_in, const int* in_sizes, int n_in,
                              void* d_out, int out_size) {
    const float* xyz     = (const float*)d_in[0];
    const float* feature = (const float*)d_in[1];
    const int*   si      = (const int*)  d_in[2];
    const float* Ww    = (const float*)d_in[3];
    const float* bw    = (const float*)d_in[4];
    const float* gw    = (const float*)d_in[5];
    const float* betaw = (const float*)d_in[6];
    const float* Wb    = (const float*)d_in[7];
    const float* bb    = (const float*)d_in[8];
    const float* gb    = (const float*)d_in[9];
    const float* betab = (const float*)d_in[10];
    const float* Wo    = (const float*)d_in[11];
    const float* bo    = (const float*)d_in[12];
    const float* go    = (const float*)d_in[13];
    const float* betao = (const float*)d_in[14];

    float* out        = (float*)d_out;
    float* out_xyz_s  = out;                                  // 4096*3
    float* out_feat   = out + S_PTS * 3;                      // 4096*128
    float* out_rf     = out_feat + S_PTS * 128;               // 4096*16*28
    float* out_ni     = out_rf + (size_t)S_PTS * KNN * 28;    // 4096*16

    prep_kernel<<<(N_PTS + 255) / 256, 256>>>(xyz, si, out_xyz_s);
    knn_kernel<<<(S_PTS + S_PTS) / 8, 256>>>(out_ni);          // 1024 blocks
    rf_adf_kernel<<<272, 256>>>(out_rf, si);
    mlp1_kernel<<<64, 256>>>(Ww, bw, gw, betaw, Wb, bb, gb, betab, feature, si);
    gemm2_kernel<<<(S_PTS * 128) / 256, 256>>>(Wo, bo);
    bnpw2_kernel<<<128, 256>>>(go, betao, out_feat);
}

// round 7
// speedup vs baseline: 7.6812x; 1.1117x over previous
#include <cuda_runtime.h>
#include <math.h>

#define N_PTS 8192
#define S_PTS 4096
#define KNN   16
#define FULLM 0xffffffffu

// ---------------- scratch (__device__ globals; no allocation allowed) ----------------
__device__ float4 g_pts[N_PTS];          // x,y,z,sq original points
__device__ float4 g_pts_s[S_PTS];        // x,y,z,sq sampled points
__device__ int    g_ni_after[S_PTS * KNN];
__device__ int4   g_anch_a[S_PTS];       // first 4 after-neighbors (sampled idx)
__device__ int4   g_anch_b[S_PTS];       // first 4 before-neighbors (global idx)
__device__ float  g_intra_a8[S_PTS * 8]; // 6 intra dists, padded to 8
__device__ float  g_intra_b8[S_PTS * 8];
__device__ float  g_adf[S_PTS * 28];
__device__ float  g_fmT[64 * S_PTS];     // transposed: [ch][s]
__device__ float  g_z[S_PTS * 128];

// ---------------- reference-rounding helpers ----------------
__device__ __forceinline__ float sq_ref(float x, float y, float z) {
    return __fadd_rn(__fadd_rn(__fmul_rn(x, x), __fmul_rn(y, y)), __fmul_rn(z, z));
}
// dot: cuBLAS SGEMM K=3 fma chain, acc0 = rn(x*x'); d2: rn elementwise fusion
__device__ __forceinline__ float d2_ref(float4 a, float4 b) {
    float dot = fmaf(a.z, b.z, fmaf(a.y, b.y, __fmul_rn(a.x, b.x)));
    float d2  = __fsub_rn(__fadd_rn(a.w, b.w), __fmul_rn(2.0f, dot));
    return fmaxf(d2, 0.0f);
}
__device__ __forceinline__ float d_ref(float4 a, float4 b) {
    float d2 = d2_ref(a, b);
    return d2 > 0.0f ? __fsqrt_rn(d2) : 0.0f;
}
__device__ __forceinline__ float leaky(float v) {
    return v >= 0.0f ? v : 0.2f * v;
}
__device__ __forceinline__ unsigned long long kmin64(unsigned long long a, unsigned long long b) {
    return a < b ? a : b;
}
__device__ __forceinline__ unsigned long long kmax64(unsigned long long a, unsigned long long b) {
    return a > b ? a : b;
}

// ---------------- prep ----------------
__global__ void prep_kernel(const float* __restrict__ xyz,
                            const int* __restrict__ si,
                            float* __restrict__ out_xyz_s) {
    int i = blockIdx.x * blockDim.x + threadIdx.x;
    if (i < N_PTS) {
        float x = xyz[3 * i], y = xyz[3 * i + 1], z = xyz[3 * i + 2];
        g_pts[i] = make_float4(x, y, z, sq_ref(x, y, z));
    }
    if (i < S_PTS) {
        int g = si[i];
        float x = xyz[3 * g], y = xyz[3 * g + 1], z = xyz[3 * g + 2];
        g_pts_s[i] = make_float4(x, y, z, sq_ref(x, y, z));
        out_xyz_s[3 * i]     = x;
        out_xyz_s[3 * i + 1] = y;
        out_xyz_s[3 * i + 2] = z;
    }
}

// ---------------- KNN: warp-per-query, lane-distributed sorted top-K ----------------
// key = (f32bits(d) << 13) | idx : integer order == lex (d, idx), tie -> lower index,
// exactly jax.lax.top_k(-D). List one element per lane (lanes 0..K-1); warp-collective
// insert via ballot position + shfl_up shift.
template <int K, int NC, bool AFTER>
__device__ __forceinline__ void knn_warp(int q, int lane, float* __restrict__ out_ni_f) {
    const float4* __restrict__ cand = AFTER ? g_pts_s : g_pts;
    float4 qp = g_pts_s[q];

    // init: exact keys of first 32 candidates, bitonic sort ascending
    float4 c0 = cand[lane];
    float d0 = d_ref(qp, c0);
    unsigned long long key = ((unsigned long long)__float_as_uint(d0) << 13) | (unsigned)lane;
#pragma unroll
    for (int k = 2; k <= 32; k <<= 1) {
#pragma unroll
        for (int j = k >> 1; j > 0; j >>= 1) {
            unsigned long long other = __shfl_xor_sync(FULLM, key, j);
            bool takemin = (((lane & k) == 0) == ((lane & j) == 0));
            key = takemin ? kmin64(key, other) : kmax64(key, other);
        }
    }
    if (lane >= K) key = ~0ull;   // ranks >= K of first 32 are dominated

    unsigned long long kth = __shfl_sync(FULLM, key, K - 1);
    float dk = __uint_as_float((unsigned)(kth >> 13));
    float thrf = fmaf(dk, dk, 1e-3f);   // conservative fma-domain superset of d <= d_K

    for (int t = 32; t < NC; t += 32) {
        float4 cp = cand[t + lane];
        float dotf = fmaf(qp.z, cp.z, fmaf(qp.y, cp.y, qp.x * cp.x));
        float d2f  = fmaf(-2.0f, dotf, qp.w + cp.w);
        bool surv = d2f < thrf;
        unsigned long long nk = ~0ull;
        if (surv) {
            float de = d_ref(qp, cp);   // exact reference arithmetic
            nk = ((unsigned long long)__float_as_uint(de) << 13) | (unsigned)(t + lane);
        }
        unsigned bal = __ballot_sync(FULLM, surv);
        if (bal) {
            do {                                      // ascending lane = ascending idx
                int pl = __ffs(bal) - 1;
                bal &= bal - 1;
                unsigned long long ck = __shfl_sync(FULLM, nk, pl);
                unsigned lt = __ballot_sync(FULLM, ck < key);
                int pos = __ffs(lt) - 1;              // uniform across warp
                if (pos < K) {
                    unsigned long long up = __shfl_up_sync(FULLM, key, 1);
                    if (lane == pos)      key = ck;
                    else if (lane > pos)  key = up;
                    if (lane >= K)        key = ~0ull;
                }
            } while (bal);
            kth  = __shfl_sync(FULLM, key, K - 1);
            dk   = __uint_as_float((unsigned)(kth >> 13));
            thrf = fmaf(dk, dk, 1e-3f);
        }
    }

    int idx = (int)(key & 0x1FFFu);
    if (AFTER && lane < K) {
        g_ni_after[q * KNN + lane] = idx;
        out_ni_f[q * KNN + lane]   = (float)idx;
    }
    unsigned long long k1 = __shfl_sync(FULLM, key, 1);
    unsigned long long k2 = __shfl_sync(FULLM, key, 2);
    unsigned long long k3 = __shfl_sync(FULLM, key, 3);
    if (lane == 0) {
        int i1 = (int)(k1 & 0x1FFF), i2 = (int)(k2 & 0x1FFF), i3 = (int)(k3 & 0x1FFF);
        float d1  = __uint_as_float((unsigned)(k1 >> 13));
        float d2v = __uint_as_float((unsigned)(k2 >> 13));
        float d3  = __uint_as_float((unsigned)(k3 >> 13));
        float4 A1 = cand[i1], A2 = cand[i2], A3 = cand[i3];
        float* intra = AFTER ? (g_intra_a8 + q * 8) : (g_intra_b8 + q * 8);
        *(float4*)intra       = make_float4(d1, d2v, d3, d_ref(A1, A2));
        *(float4*)(intra + 4) = make_float4(d_ref(A1, A3), d_ref(A2, A3), 0.0f, 0.0f);
        if (AFTER) g_anch_a[q] = make_int4(idx, i1, i2, i3);
        else       g_anch_b[q] = make_int4(idx, i1, i2, i3);
    }
}

__global__ void __launch_bounds__(256) knn_kernel(float* __restrict__ out_ni_f) {
    int gw   = blockIdx.x * 8 + (threadIdx.x >> 5);
    int lane = threadIdx.x & 31;
    if (gw < S_PTS) knn_warp<KNN, S_PTS, true >(gw, lane, out_ni_f);
    else            knn_warp<4,   N_PTS, false>(gw - S_PTS, lane, out_ni_f);
}

// ---------------- fused rf (512 blocks, 2 threads/row) + adf (16 blocks) ----------------
__global__ void __launch_bounds__(256) rf_adf_kernel(float* __restrict__ out_rf,
                                                     const int* __restrict__ si) {
    int b = blockIdx.x;
    if (b < 512) {
        int id = b * 256 + threadIdx.x;           // < 131072
        int i = id >> 1, h = id & 1;              // row, half
        int n = i >> 4, k = i & 15;
        int nb = g_ni_after[n * KNN + k];
        int4 an  = g_anch_a[n];
        int4 anb = g_anch_a[nb];
        float4 Q0 = g_pts_s[anb.x], Q1 = g_pts_s[anb.y], Q2 = g_pts_s[anb.z], Q3 = g_pts_s[anb.w];
        float* o = out_rf + (size_t)i * 28;
        if (h == 0) {
            float4 a0 = *(const float4*)(g_intra_a8 + n * 8);
            float4 a1 = *(const float4*)(g_intra_a8 + n * 8 + 4);
            float4 c0 = *(const float4*)(g_intra_a8 + nb * 8);
            float4 c1 = *(const float4*)(g_intra_a8 + nb * 8 + 4);
            float4 P0 = g_pts_s[an.x], P1 = g_pts_s[an.y];
            ((float4*)o)[0] = make_float4(a0.x, a0.y, a0.z, a0.w);
            ((float4*)o)[1] = make_float4(a1.x, a1.y, c0.x, c0.y);
            ((float4*)o)[2] = make_float4(c0.z, c0.w, c1.x, c1.y);
            ((float4*)o)[3] = make_float4(d_ref(P0,Q0), d_ref(P0,Q1), d_ref(P0,Q2), d_ref(P0,Q3));
            ((float4*)o)[4] = make_float4(d_ref(P1,Q0), d_ref(P1,Q1), d_ref(P1,Q2), d_ref(P1,Q3));
        } else {
            float4 P2 = g_pts_s[an.z], P3 = g_pts_s[an.w];
            ((float4*)o)[5] = make_float4(d_ref(P2,Q0), d_ref(P2,Q1), d_ref(P2,Q2), d_ref(P2,Q3));
            ((float4*)o)[6] = make_float4(d_ref(P3,Q0), d_ref(P3,Q1), d_ref(P3,Q2), d_ref(P3,Q3));
        }
    } else {
        int s = (b - 512) * 256 + threadIdx.x;    // < 4096
        float4 b0 = *(const float4*)(g_intra_b8 + s * 8);
        float4 b1 = *(const float4*)(g_intra_b8 + s * 8 + 4);
        float4 a0 = *(const float4*)(g_intra_a8 + s * 8);
        float4 a1 = *(const float4*)(g_intra_a8 + s * 8 + 4);
        int4 ab = g_anch_b[s];
        int4 aa = g_anch_a[s];
        float4 P0 = g_pts[ab.x], P1 = g_pts[ab.y], P2 = g_pts[ab.z], P3 = g_pts[ab.w];
        float4 Q0 = g_pts[si[aa.x]], Q1 = g_pts[si[aa.y]], Q2 = g_pts[si[aa.z]], Q3 = g_pts[si[aa.w]];
        float* o = g_adf + s * 28;
        ((float4*)o)[0] = make_float4(b0.x, b0.y, b0.z, b0.w);
        ((float4*)o)[1] = make_float4(b1.x, b1.y, a0.x, a0.y);
        ((float4*)o)[2] = make_float4(a0.z, a0.w, a1.x, a1.y);
        ((float4*)o)[3] = make_float4(d_ref(P0,Q0), d_ref(P0,Q1), d_ref(P0,Q2), d_ref(P0,Q3));
        ((float4*)o)[4] = make_float4(d_ref(P1,Q0), d_ref(P1,Q1), d_ref(P1,Q2), d_ref(P1,Q3));
        ((float4*)o)[5] = make_float4(d_ref(P2,Q0), d_ref(P2,Q1), d_ref(P2,Q2), d_ref(P2,Q3));
        ((float4*)o)[6] = make_float4(d_ref(P3,Q0), d_ref(P3,Q1), d_ref(P3,Q2), d_ref(P3,Q3));
    }
}

// ---------------- mlp1: gemm1(w,b) + BN stats + pw1 fused, one block per channel ----------------
// adf staged through smem with coalesced float4 loads; row padded to 29 floats
// (29*drow mod 32 => conflict-free LDS). y values live in registers.
__global__ void __launch_bounds__(256) mlp1_kernel(
    const float* __restrict__ Ww, const float* __restrict__ bw,
    const float* __restrict__ gw, const float* __restrict__ betaw,
    const float* __restrict__ Wb, const float* __restrict__ bb,
    const float* __restrict__ gb, const float* __restrict__ betab,
    const float* __restrict__ feature, const int* __restrict__ si) {
    __shared__ float wws[28], wbs[28];
    __shared__ float tile[256 * 29];
    __shared__ float red[256], red2[256];
    __shared__ float stats[4];
    int ch = blockIdx.x, tid = threadIdx.x;
    if (tid < 28) { wws[tid] = Ww[tid * 64 + ch]; wbs[tid] = Wb[tid * 64 + ch]; }
    float bwv = bw[ch], bbv = bb[ch];
    float yw[16], yb[16];
    float sw = 0.f, s2w = 0.f, sb = 0.f, s2b = 0.f;
    for (int t = 0; t < 16; t++) {
        const float4* src = (const float4*)(g_adf + t * 256 * 28);
        __syncthreads();                        // previous-iter reads done (also covers wws/wbs)
#pragma unroll
        for (int k = 0; k < 7; k++) {
            int fi = k * 256 + tid;             // 1792 float4s, coalesced
            float4 v = src[fi];
            float* d = tile + (fi / 7) * 29 + (fi % 7) * 4;
            d[0] = v.x; d[1] = v.y; d[2] = v.z; d[3] = v.w;
        }
        __syncthreads();
        const float* r = tile + tid * 29;
        float vw = bwv, vb = bbv;
#pragma unroll
        for (int c = 0; c < 28; c++) {
            float av = r[c];
            vw = fmaf(av, wws[c], vw);
            vb = fmaf(av, wbs[c], vb);
        }
        yw[t] = vw; yb[t] = vb;
        sw += vw; s2w = fmaf(vw, vw, s2w);
        sb += vb; s2b = fmaf(vb, vb, s2b);
    }
    red[tid] = sw; red2[tid] = s2w; __syncthreads();
    for (int st = 128; st > 0; st >>= 1) {
        if (tid < st) { red[tid] += red[tid + st]; red2[tid] += red2[tid + st]; }
        __syncthreads();
    }
    if (tid == 0) {
        float mu = red[0] / (float)S_PTS;
        float var = red2[0] / (float)S_PTS - mu * mu;
        stats[0] = mu; stats[1] = rsqrtf(var + 1e-5f);
    }
    __syncthreads();
    red[tid] = sb; red2[tid] = s2b; __syncthreads();
    for (int st = 128; st > 0; st >>= 1) {
        if (tid < st) { red[tid] += red[tid + st]; red2[tid] += red2[tid + st]; }
        __syncthreads();
    }
    if (tid == 0) {
        float mu = red[0] / (float)S_PTS;
        float var = red2[0] / (float)S_PTS - mu * mu;
        stats[2] = mu; stats[3] = rsqrtf(var + 1e-5f);
    }
    __syncthreads();
    float muw = stats[0], rsw = stats[1], mub = stats[2], rsb = stats[3];
    float gwv = gw[ch], bew = betaw[ch], gbv = gb[ch], beb = betab[ch];
#pragma unroll
    for (int t = 0; t < 16; t++) {
        int s = t * 256 + tid;
        float w = (yw[t] - muw) * rsw * gwv + bew;
        float b = (yb[t] - mub) * rsb * gbv + beb;
        float f = feature[si[s] * 64 + ch];
        g_fmT[ch * S_PTS + s] = leaky(fmaf(f, w, b));   // coalesced store
    }
}

// ---------------- GEMM2: z = [fm | adf] @ Wo + bo  (fm broadcast, Wo coalesced) ----------------
__global__ void gemm2_kernel(const float* __restrict__ Wo, const float* __restrict__ bo) {
    int tid = blockIdx.x * blockDim.x + threadIdx.x;
    int ch = tid & 127, s = tid >> 7;
    if (s >= S_PTS) return;
    float acc = bo[ch];
#pragma unroll
    for (int c = 0; c < 64; c++) acc = fmaf(g_fmT[c * S_PTS + s], Wo[c * 128 + ch], acc);
    const float* a = g_adf + s * 28;
#pragma unroll
    for (int c = 0; c < 28; c++) acc = fmaf(a[c], Wo[(64 + c) * 128 + ch], acc);
    g_z[s * 128 + ch] = acc;
}

// ---------------- bnpw2: BN stats + affine + leaky, 4 channels/block, float4 I/O ----------------
__global__ void __launch_bounds__(256) bnpw2_kernel(const float* __restrict__ go,
                                                    const float* __restrict__ betao,
                                                    float* __restrict__ out_feat) {
    __shared__ float4 red[256], red2[256];
    __shared__ float4 stats[2];
    int ch4 = blockIdx.x * 4, tid = threadIdx.x;
    float4 v[16];
    float4 s  = make_float4(0.f, 0.f, 0.f, 0.f);
    float4 s2 = make_float4(0.f, 0.f, 0.f, 0.f);
#pragma unroll
    for (int i = 0; i < 16; i++) {
        int r = i * 256 + tid;
        float4 val = *(const float4*)(g_z + (size_t)r * 128 + ch4);
        v[i] = val;
        s.x += val.x; s.y += val.y; s.z += val.z; s.w += val.w;
        s2.x = fmaf(val.x, val.x, s2.x); s2.y = fmaf(val.y, val.y, s2.y);
        s2.z = fmaf(val.z, val.z, s2.z); s2.w = fmaf(val.w, val.w, s2.w);
    }
    red[tid] = s; red2[tid] = s2;
    __syncthreads();
    for (int st = 128; st > 0; st >>= 1) {
        if (tid < st) {
            float4 a = red[tid + st], a2 = red2[tid + st];
            red[tid].x += a.x; red[tid].y += a.y; red[tid].z += a.z; red[tid].w += a.w;
            red2[tid].x += a2.x; red2[tid].y += a2.y; red2[tid].z += a2.z; red2[tid].w += a2.w;
        }
        __syncthreads();
    }
    if (tid == 0) {
        float4 sum = red[0], sum2 = red2[0];
        float4 mu = make_float4(sum.x / S_PTS, sum.y / S_PTS, sum.z / S_PTS, sum.w / S_PTS);
        stats[0] = mu;
        stats[1] = make_float4(rsqrtf(sum2.x / S_PTS - mu.x * mu.x + 1e-5f),
                               rsqrtf(sum2.y / S_PTS - mu.y * mu.y + 1e-5f),
                               rsqrtf(sum2.z / S_PTS - mu.z * mu.z + 1e-5f),
                               rsqrtf(sum2.w / S_PTS - mu.w * mu.w + 1e-5f));
    }
    __syncthreads();
    float4 mu = stats[0], rs = stats[1];
    float4 g  = *(const float4*)(go + ch4);
    float4 be = *(const float4*)(betao + ch4);
#pragma unroll
    for (int i = 0; i < 16; i++) {
        int r = i * 256 + tid;
        float4 val = v[i];
        float4 o;
        o.x = leaky((val.x - mu.x) * rs.x * g.x + be.x);
        o.y = leaky((val.y - mu.y) * rs.y * g.y + be.y);
        o.z = leaky((val.z - mu.z) * rs.z * g.z + be.z);
        o.w = leaky((val.w - mu.w) * rs.w * g.w + be.w);
        *(float4*)(out_feat + (size_t)r * 128 + ch4) = o;
    }
}

// ---------------- launch ----------------
extern "C" void kernel_launch(void* const* d_in, const int* in_sizes, int n_in,
                              void* d_out, int out_size) {
    const float* xyz     = (const float*)d_in[0];
    const float* feature = (const float*)d_in[1];
    const int*   si      = (const int*)  d_in[2];
    const float* Ww    = (const float*)d_in[3];
    const float* bw    = (const float*)d_in[4];
    const float* gw    = (const float*)d_in[5];
    const float* betaw = (const float*)d_in[6];
    const float* Wb    = (const float*)d_in[7];
    const float* bb    = (const float*)d_in[8];
    const float* gb    = (const float*)d_in[9];
    const float* betab = (const float*)d_in[10];
    const float* Wo    = (const float*)d_in[11];
    const float* bo    = (const float*)d_in[12];
    const float* go    = (const float*)d_in[13];
    const float* betao = (const float*)d_in[14];

    float* out        = (float*)d_out;
    float* out_xyz_s  = out;                                  // 4096*3
    float* out_feat   = out + S_PTS * 3;                      // 4096*128
    float* out_rf     = out_feat + S_PTS * 128;               // 4096*16*28
    float* out_ni     = out_rf + (size_t)S_PTS * KNN * 28;    // 4096*16

    prep_kernel<<<(N_PTS + 255) / 256, 256>>>(xyz, si, out_xyz_s);
    knn_kernel<<<(S_PTS + S_PTS) / 8, 256>>>(out_ni);          // 1024 blocks
    rf_adf_kernel<<<528, 256>>>(out_rf, si);
    mlp1_kernel<<<64, 256>>>(Ww, bw, gw, betaw, Wb, bb, gb, betab, feature, si);
    gemm2_kernel<<<(S_PTS * 128) / 256, 256>>>(Wo, bo);
    bnpw2_kernel<<<32, 256>>>(go, betao, out_feat);
}

// round 8
// speedup vs baseline: 8.2686x; 1.0765x over previous
#include <cuda_runtime.h>
#include <math.h>

#define N_PTS 8192
#define S_PTS 4096
#define KNN   16
#define FULLM 0xffffffffu

// ---------------- scratch (__device__ globals; no allocation allowed) ----------------
__device__ float4 g_pts[N_PTS];          // x,y,z,sq original points
__device__ float4 g_pts_s[S_PTS];        // x,y,z,sq sampled points
__device__ int    g_ni_after[S_PTS * KNN];
__device__ int4   g_anch_a[S_PTS];       // first 4 after-neighbors (sampled idx)
__device__ int4   g_anch_b[S_PTS];       // first 4 before-neighbors (global idx)
__device__ float  g_intra_a8[S_PTS * 8]; // 6 intra dists, padded to 8
__device__ float  g_intra_b8[S_PTS * 8];
__device__ float  g_adf[S_PTS * 28];
__device__ float  g_y[S_PTS * 128];      // [s][0:64)=yw, [s][64:128)=yb
__device__ float  g_fmT[64 * S_PTS];     // transposed: [ch][s]
__device__ float  g_z[S_PTS * 128];

// ---------------- reference-rounding helpers ----------------
__device__ __forceinline__ float sq_ref(float x, float y, float z) {
    return __fadd_rn(__fadd_rn(__fmul_rn(x, x), __fmul_rn(y, y)), __fmul_rn(z, z));
}
// dot: cuBLAS SGEMM K=3 fma chain, acc0 = rn(x*x'); d2: rn elementwise fusion
__device__ __forceinline__ float d2_ref(float4 a, float4 b) {
    float dot = fmaf(a.z, b.z, fmaf(a.y, b.y, __fmul_rn(a.x, b.x)));
    float d2  = __fsub_rn(__fadd_rn(a.w, b.w), __fmul_rn(2.0f, dot));
    return fmaxf(d2, 0.0f);
}
__device__ __forceinline__ float d_ref(float4 a, float4 b) {
    float d2 = d2_ref(a, b);
    return d2 > 0.0f ? __fsqrt_rn(d2) : 0.0f;
}
__device__ __forceinline__ float leaky(float v) {
    return v >= 0.0f ? v : 0.2f * v;
}
__device__ __forceinline__ unsigned long long kmin64(unsigned long long a, unsigned long long b) {
    return a < b ? a : b;
}
__device__ __forceinline__ unsigned long long kmax64(unsigned long long a, unsigned long long b) {
    return a > b ? a : b;
}
__device__ __forceinline__ unsigned long long mk_key(float d, unsigned idx) {
    return ((unsigned long long)__float_as_uint(d) << 13) | idx;
}

// ---------------- prep ----------------
__global__ void prep_kernel(const float* __restrict__ xyz,
                            const int* __restrict__ si,
                            float* __restrict__ out_xyz_s) {
    int i = blockIdx.x * blockDim.x + threadIdx.x;
    if (i < N_PTS) {
        float x = xyz[3 * i], y = xyz[3 * i + 1], z = xyz[3 * i + 2];
        g_pts[i] = make_float4(x, y, z, sq_ref(x, y, z));
    }
    if (i < S_PTS) {
        int g = si[i];
        float x = xyz[3 * g], y = xyz[3 * g + 1], z = xyz[3 * g + 2];
        g_pts_s[i] = make_float4(x, y, z, sq_ref(x, y, z));
        out_xyz_s[3 * i]     = x;
        out_xyz_s[3 * i + 1] = y;
        out_xyz_s[3 * i + 2] = z;
    }
}

// ---------------- KNN: warp per 2 queries, lane-distributed sorted top-K ----------------
// key = (f32bits(d) << 13) | idx : integer order == lex (d, idx), tie -> lower index,
// exactly jax.lax.top_k(-D). List one element per lane (lanes 0..K-1); warp-collective
// insert via ballot position + shfl_up shift. Each candidate float4 is loaded ONCE and
// scored against both register-resident queries (halves L1 traffic).
__device__ __forceinline__ unsigned long long bitonic32(unsigned long long key, int lane) {
#pragma unroll
    for (int k = 2; k <= 32; k <<= 1) {
#pragma unroll
        for (int j = k >> 1; j > 0; j >>= 1) {
            unsigned long long other = __shfl_xor_sync(FULLM, key, j);
            bool takemin = (((lane & k) == 0) == ((lane & j) == 0));
            key = takemin ? kmin64(key, other) : kmax64(key, other);
        }
    }
    return key;
}

template <int K>
__device__ __forceinline__ void insert_surv(unsigned bal, unsigned long long nk,
                                            unsigned long long& key, float& thrf, int lane) {
    if (!bal) return;
    do {                                      // ascending lane = ascending idx
        int pl = __ffs(bal) - 1;
        bal &= bal - 1;
        unsigned long long ck = __shfl_sync(FULLM, nk, pl);
        unsigned lt = __ballot_sync(FULLM, ck < key);
        int pos = __ffs(lt) - 1;              // uniform across warp
        if (pos < K) {
            unsigned long long up = __shfl_up_sync(FULLM, key, 1);
            if (lane == pos)      key = ck;
            else if (lane > pos)  key = up;
            if (lane >= K)        key = ~0ull;
        }
    } while (bal);
    unsigned long long kth = __shfl_sync(FULLM, key, K - 1);
    float dk = __uint_as_float((unsigned)(kth >> 13));
    thrf = fmaf(dk, dk, 1e-3f);
}

template <int K, bool AFTER>
__device__ __forceinline__ void emit_knn(unsigned long long key, int q, int lane,
                                         const float4* __restrict__ cand,
                                         float* __restrict__ out_ni_f) {
    int idx = (int)(key & 0x1FFFu);
    if (AFTER && lane < K) {
        g_ni_after[q * KNN + lane] = idx;
        out_ni_f[q * KNN + lane]   = (float)idx;
    }
    unsigned long long k1 = __shfl_sync(FULLM, key, 1);
    unsigned long long k2 = __shfl_sync(FULLM, key, 2);
    unsigned long long k3 = __shfl_sync(FULLM, key, 3);
    if (lane == 0) {
        int i1 = (int)(k1 & 0x1FFF), i2 = (int)(k2 & 0x1FFF), i3 = (int)(k3 & 0x1FFF);
        float d1  = __uint_as_float((unsigned)(k1 >> 13));
        float d2v = __uint_as_float((unsigned)(k2 >> 13));
        float d3  = __uint_as_float((unsigned)(k3 >> 13));
        float4 A1 = cand[i1], A2 = cand[i2], A3 = cand[i3];
        float* intra = AFTER ? (g_intra_a8 + q * 8) : (g_intra_b8 + q * 8);
        *(float4*)intra       = make_float4(d1, d2v, d3, d_ref(A1, A2));
        *(float4*)(intra + 4) = make_float4(d_ref(A1, A3), d_ref(A2, A3), 0.0f, 0.0f);
        if (AFTER) g_anch_a[q] = make_int4(idx, i1, i2, i3);
        else       g_anch_b[q] = make_int4(idx, i1, i2, i3);
    }
}

template <int K, int NC, bool AFTER>
__device__ __forceinline__ void knn_warp2(int q0, int lane, float* __restrict__ out_ni_f) {
    const float4* __restrict__ cand = AFTER ? g_pts_s : g_pts;
    float4 qp0 = g_pts_s[q0];
    float4 qp1 = g_pts_s[q0 + 1];

    // init: exact keys of first 32 candidates, bitonic sort ascending
    float4 c0 = cand[lane];
    unsigned long long key0 = bitonic32(mk_key(d_ref(qp0, c0), (unsigned)lane), lane);
    unsigned long long key1 = bitonic32(mk_key(d_ref(qp1, c0), (unsigned)lane), lane);
    if (lane >= K) { key0 = ~0ull; key1 = ~0ull; }   // ranks >= K dominated

    unsigned long long kth0 = __shfl_sync(FULLM, key0, K - 1);
    unsigned long long kth1 = __shfl_sync(FULLM, key1, K - 1);
    float dk0 = __uint_as_float((unsigned)(kth0 >> 13));
    float dk1 = __uint_as_float((unsigned)(kth1 >> 13));
    float thr0 = fmaf(dk0, dk0, 1e-3f);   // conservative fma-domain superset of d <= d_K
    float thr1 = fmaf(dk1, dk1, 1e-3f);

    for (int t = 32; t < NC; t += 32) {
        float4 cp = cand[t + lane];
        float dot0 = fmaf(qp0.z, cp.z, fmaf(qp0.y, cp.y, qp0.x * cp.x));
        float dot1 = fmaf(qp1.z, cp.z, fmaf(qp1.y, cp.y, qp1.x * cp.x));
        float d2f0 = fmaf(-2.0f, dot0, qp0.w + cp.w);
        float d2f1 = fmaf(-2.0f, dot1, qp1.w + cp.w);
        bool s0 = d2f0 < thr0;
        bool s1 = d2f1 < thr1;
        unsigned long long nk0 = ~0ull, nk1 = ~0ull;
        if (s0) nk0 = mk_key(d_ref(qp0, cp), (unsigned)(t + lane));  // exact reference math
        if (s1) nk1 = mk_key(d_ref(qp1, cp), (unsigned)(t + lane));
        unsigned bal0 = __ballot_sync(FULLM, s0);
        unsigned bal1 = __ballot_sync(FULLM, s1);
        insert_surv<K>(bal0, nk0, key0, thr0, lane);
        insert_surv<K>(bal1, nk1, key1, thr1, lane);
    }

    emit_knn<K, AFTER>(key0, q0,     lane, cand, out_ni_f);
    emit_knn<K, AFTER>(key1, q0 + 1, lane, cand, out_ni_f);
}

__global__ void __launch_bounds__(256) knn_kernel(float* __restrict__ out_ni_f) {
    int gw   = blockIdx.x * 8 + (threadIdx.x >> 5);   // 4096 warps total
    int lane = threadIdx.x & 31;
    if (gw < S_PTS / 2) knn_warp2<KNN, S_PTS, true >(gw * 2, lane, out_ni_f);
    else                knn_warp2<4,   N_PTS, false>((gw - S_PTS / 2) * 2, lane, out_ni_f);
}

// ---------------- fused rf (512 blocks, 2 threads/row) + adf (16 blocks) ----------------
__global__ void __launch_bounds__(256) rf_adf_kernel(float* __restrict__ out_rf,
                                                     const int* __restrict__ si) {
    int b = blockIdx.x;
    if (b < 512) {
        int id = b * 256 + threadIdx.x;           // < 131072
        int i = id >> 1, h = id & 1;              // row, half
        int n = i >> 4, k = i & 15;
        int nb = g_ni_after[n * KNN + k];
        int4 an  = g_anch_a[n];
        int4 anb = g_anch_a[nb];
        float4 Q0 = g_pts_s[anb.x], Q1 = g_pts_s[anb.y], Q2 = g_pts_s[anb.z], Q3 = g_pts_s[anb.w];
        float* o = out_rf + (size_t)i * 28;
        if (h == 0) {
            float4 a0 = *(const float4*)(g_intra_a8 + n * 8);
            float4 a1 = *(const float4*)(g_intra_a8 + n * 8 + 4);
            float4 c0 = *(const float4*)(g_intra_a8 + nb * 8);
            float4 c1 = *(const float4*)(g_intra_a8 + nb * 8 + 4);
            float4 P0 = g_pts_s[an.x], P1 = g_pts_s[an.y];
            ((float4*)o)[0] = make_float4(a0.x, a0.y, a0.z, a0.w);
            ((float4*)o)[1] = make_float4(a1.x, a1.y, c0.x, c0.y);
            ((float4*)o)[2] = make_float4(c0.z, c0.w, c1.x, c1.y);
            ((float4*)o)[3] = make_float4(d_ref(P0,Q0), d_ref(P0,Q1), d_ref(P0,Q2), d_ref(P0,Q3));
            ((float4*)o)[4] = make_float4(d_ref(P1,Q0), d_ref(P1,Q1), d_ref(P1,Q2), d_ref(P1,Q3));
        } else {
            float4 P2 = g_pts_s[an.z], P3 = g_pts_s[an.w];
            ((float4*)o)[5] = make_float4(d_ref(P2,Q0), d_ref(P2,Q1), d_ref(P2,Q2), d_ref(P2,Q3));
            ((float4*)o)[6] = make_float4(d_ref(P3,Q0), d_ref(P3,Q1), d_ref(P3,Q2), d_ref(P3,Q3));
        }
    } else {
        int s = (b - 512) * 256 + threadIdx.x;    // < 4096
        float4 b0 = *(const float4*)(g_intra_b8 + s * 8);
        float4 b1 = *(const float4*)(g_intra_b8 + s * 8 + 4);
        float4 a0 = *(const float4*)(g_intra_a8 + s * 8);
        float4 a1 = *(const float4*)(g_intra_a8 + s * 8 + 4);
        int4 ab = g_anch_b[s];
        int4 aa = g_anch_a[s];
        float4 P0 = g_pts[ab.x], P1 = g_pts[ab.y], P2 = g_pts[ab.z], P3 = g_pts[ab.w];
        float4 Q0 = g_pts[si[aa.x]], Q1 = g_pts[si[aa.y]], Q2 = g_pts[si[aa.z]], Q3 = g_pts[si[aa.w]];
        float* o = g_adf + s * 28;
        ((float4*)o)[0] = make_float4(b0.x, b0.y, b0.z, b0.w);
        ((float4*)o)[1] = make_float4(b1.x, b1.y, a0.x, a0.y);
        ((float4*)o)[2] = make_float4(a0.z, a0.w, a1.x, a1.y);
        ((float4*)o)[3] = make_float4(d_ref(P0,Q0), d_ref(P0,Q1), d_ref(P0,Q2), d_ref(P0,Q3));
        ((float4*)o)[4] = make_float4(d_ref(P1,Q0), d_ref(P1,Q1), d_ref(P1,Q2), d_ref(P1,Q3));
        ((float4*)o)[5] = make_float4(d_ref(P2,Q0), d_ref(P2,Q1), d_ref(P2,Q2), d_ref(P2,Q3));
        ((float4*)o)[6] = make_float4(d_ref(P3,Q0), d_ref(P3,Q1), d_ref(P3,Q2), d_ref(P3,Q3));
    }
}

// ---------------- gemm1: y = adf @ {Ww|Wb} + {bw|bb}, thread per (s,ch) ----------------
// Same fma order as the previous fused kernel -> bitwise-identical y.
__global__ void __launch_bounds__(256) gemm1_kernel(
    const float* __restrict__ Ww, const float* __restrict__ bw,
    const float* __restrict__ Wb, const float* __restrict__ bb) {
    int tid = blockIdx.x * blockDim.x + threadIdx.x;
    int ch = tid & 63, s = tid >> 6;
    float aw = bw[ch], ab = bb[ch];
    const float* a = g_adf + s * 28;
#pragma unroll
    for (int c = 0; c < 28; c++) {
        float av = a[c];
        aw = fmaf(av, Ww[c * 64 + ch], aw);
        ab = fmaf(av, Wb[c * 64 + ch], ab);
    }
    g_y[s * 128 + ch]      = aw;
    g_y[s * 128 + 64 + ch] = ab;
}

// ---------------- statspw1: BN stats (w & b) + gate + leaky, 2 channels/block ----------------
// Per-thread row order identical to the previous fused kernel -> bitwise-identical stats.
__global__ void __launch_bounds__(256) statspw1_kernel(
    const float* __restrict__ gw, const float* __restrict__ betaw,
    const float* __restrict__ gb, const float* __restrict__ betab,
    const float* __restrict__ feature, const int* __restrict__ si) {
    __shared__ float2 red[256], red2[256];
    __shared__ float  stats[8];   // muw0 muw1 rsw0 rsw1 mub0 mub1 rsb0 rsb1
    int ch2 = blockIdx.x * 2, tid = threadIdx.x;
    float2 vw[16], vb[16];
    float2 sw = make_float2(0.f, 0.f), s2w = make_float2(0.f, 0.f);
    float2 sb = make_float2(0.f, 0.f), s2b = make_float2(0.f, 0.f);
#pragma unroll
    for (int i = 0; i < 16; i++) {
        int r = i * 256 + tid;
        float2 w = *(const float2*)(g_y + (size_t)r * 128 + ch2);
        float2 b = *(const float2*)(g_y + (size_t)r * 128 + 64 + ch2);
        vw[i] = w; vb[i] = b;
        sw.x += w.x; sw.y += w.y; s2w.x = fmaf(w.x, w.x, s2w.x); s2w.y = fmaf(w.y, w.y, s2w.y);
        sb.x += b.x; sb.y += b.y; s2b.x = fmaf(b.x, b.x, s2b.x); s2b.y = fmaf(b.y, b.y, s2b.y);
    }
    red[tid] = sw; red2[tid] = s2w; __syncthreads();
    for (int st = 128; st > 0; st >>= 1) {
        if (tid < st) {
            red[tid].x += red[tid + st].x;  red[tid].y += red[tid + st].y;
            red2[tid].x += red2[tid + st].x; red2[tid].y += red2[tid + st].y;
        }
        __syncthreads();
    }
    if (tid == 0) {
        float mu0 = red[0].x / (float)S_PTS, mu1 = red[0].y / (float)S_PTS;
        stats[0] = mu0; stats[1] = mu1;
        stats[2] = rsqrtf(red2[0].x / (float)S_PTS - mu0 * mu0 + 1e-5f);
        stats[3] = rsqrtf(red2[0].y / (float)S_PTS - mu1 * mu1 + 1e-5f);
    }
    __syncthreads();
    red[tid] = sb; red2[tid] = s2b; __syncthreads();
    for (int st = 128; st > 0; st >>= 1) {
        if (tid < st) {
            red[tid].x += red[tid + st].x;  red[tid].y += red[tid + st].y;
            red2[tid].x += red2[tid + st].x; red2[tid].y += red2[tid + st].y;
        }
        __syncthreads();
    }
    if (tid == 0) {
        float mu0 = red[0].x / (float)S_PTS, mu1 = red[0].y / (float)S_PTS;
        stats[4] = mu0; stats[5] = mu1;
        stats[6] = rsqrtf(red2[0].x / (float)S_PTS - mu0 * mu0 + 1e-5f);
        stats[7] = rsqrtf(red2[0].y / (float)S_PTS - mu1 * mu1 + 1e-5f);
    }
    __syncthreads();
    float muw0 = stats[0], muw1 = stats[1], rsw0 = stats[2], rsw1 = stats[3];
    float mub0 = stats[4], mub1 = stats[5], rsb0 = stats[6], rsb1 = stats[7];
    float gw0 = gw[ch2], gw1 = gw[ch2 + 1], bew0 = betaw[ch2], bew1 = betaw[ch2 + 1];
    float gb0 = gb[ch2], gb1 = gb[ch2 + 1], beb0 = betab[ch2], beb1 = betab[ch2 + 1];
#pragma unroll
    for (int i = 0; i < 16; i++) {
        int r = i * 256 + tid;
        float2 f = *(const float2*)(feature + (size_t)si[r] * 64 + ch2);
        float w0 = (vw[i].x - muw0) * rsw0 * gw0 + bew0;
        float w1 = (vw[i].y - muw1) * rsw1 * gw1 + bew1;
        float b0 = (vb[i].x - mub0) * rsb0 * gb0 + beb0;
        float b1 = (vb[i].y - mub1) * rsb1 * gb1 + beb1;
        g_fmT[(size_t)ch2 * S_PTS + r]       = leaky(fmaf(f.x, w0, b0));
        g_fmT[(size_t)(ch2 + 1) * S_PTS + r] = leaky(fmaf(f.y, w1, b1));
    }
}

// ---------------- GEMM2: z = [fm | adf] @ Wo + bo  (fm broadcast, Wo coalesced) ----------------
__global__ void gemm2_kernel(const float* __restrict__ Wo, const float* __restrict__ bo) {
    int tid = blockIdx.x * blockDim.x + threadIdx.x;
    int ch = tid & 127, s = tid >> 7;
    if (s >= S_PTS) return;
    float acc = bo[ch];
#pragma unroll
    for (int c = 0; c < 64; c++) acc = fmaf(g_fmT[c * S_PTS + s], Wo[c * 128 + ch], acc);
    const float* a = g_adf + s * 28;
#pragma unroll
    for (int c = 0; c < 28; c++) acc = fmaf(a[c], Wo[(64 + c) * 128 + ch], acc);
    g_z[s * 128 + ch] = acc;
}

// ---------------- bnpw2: BN stats + affine + leaky, 4 channels/block, float4 I/O ----------------
__global__ void __launch_bounds__(256) bnpw2_kernel(const float* __restrict__ go,
                                                    const float* __restrict__ betao,
                                                    float* __restrict__ out_feat) {
    __shared__ float4 red[256], red2[256];
    __shared__ float4 stats[2];
    int ch4 = blockIdx.x * 4, tid = threadIdx.x;
    float4 v[16];
    float4 s  = make_float4(0.f, 0.f, 0.f, 0.f);
    float4 s2 = make_float4(0.f, 0.f, 0.f, 0.f);
#pragma unroll
    for (int i = 0; i < 16; i++) {
        int r = i * 256 + tid;
        float4 val = *(const float4*)(g_z + (size_t)r * 128 + ch4);
        v[i] = val;
        s.x += val.x; s.y += val.y; s.z += val.z; s.w += val.w;
        s2.x = fmaf(val.x, val.x, s2.x); s2.y = fmaf(val.y, val.y, s2.y);
        s2.z = fmaf(val.z, val.z, s2.z); s2.w = fmaf(val.w, val.w, s2.w);
    }
    red[tid] = s; red2[tid] = s2;
    __syncthreads();
    for (int st = 128; st > 0; st >>= 1) {
        if (tid < st) {
            float4 a = red[tid + st], a2 = red2[tid + st];
            red[tid].x += a.x; red[tid].y += a.y; red[tid].z += a.z; red[tid].w += a.w;
            red2[tid].x += a2.x; red2[tid].y += a2.y; red2[tid].z += a2.z; red2[tid].w += a2.w;
        }
        __syncthreads();
    }
    if (tid == 0) {
        float4 sum = red[0], sum2 = red2[0];
        float4 mu = make_float4(sum.x / S_PTS, sum.y / S_PTS, sum.z / S_PTS, sum.w / S_PTS);
        stats[0] = mu;
        stats[1] = make_float4(rsqrtf(sum2.x / S_PTS - mu.x * mu.x + 1e-5f),
                               rsqrtf(sum2.y / S_PTS - mu.y * mu.y + 1e-5f),
                               rsqrtf(sum2.z / S_PTS - mu.z * mu.z + 1e-5f),
                               rsqrtf(sum2.w / S_PTS - mu.w * mu.w + 1e-5f));
    }
    __syncthreads();
    float4 mu = stats[0], rs = stats[1];
    float4 g  = *(const float4*)(go + ch4);
    float4 be = *(const float4*)(betao + ch4);
#pragma unroll
    for (int i = 0; i < 16; i++) {
        int r = i * 256 + tid;
        float4 val = v[i];
        float4 o;
        o.x = leaky((val.x - mu.x) * rs.x * g.x + be.x);
        o.y = leaky((val.y - mu.y) * rs.y * g.y + be.y);
        o.z = leaky((val.z - mu.z) * rs.z * g.z + be.z);
        o.w = leaky((val.w - mu.w) * rs.w * g.w + be.w);
        *(float4*)(out_feat + (size_t)r * 128 + ch4) = o;
    }
}

// ---------------- launch ----------------
extern "C" void kernel_launch(void* const* d_in, const int* in_sizes, int n_in,
                              void* d_out, int out_size) {
    const float* xyz     = (const float*)d_in[0];
    const float* feature = (const float*)d_in[1];
    const int*   si      = (const int*)  d_in[2];
    const float* Ww    = (const float*)d_in[3];
    const float* bw    = (const float*)d_in[4];
    const float* gw    = (const float*)d_in[5];
    const float* betaw = (const float*)d_in[6];
    const float* Wb    = (const float*)d_in[7];
    const float* bb    = (const float*)d_in[8];
    const float* gb    = (const float*)d_in[9];
    const float* betab = (const float*)d_in[10];
    const float* Wo    = (const float*)d_in[11];
    const float* bo    = (const float*)d_in[12];
    const float* go    = (const float*)d_in[13];
    const float* betao = (const float*)d_in[14];

    float* out        = (float*)d_out;
    float* out_xyz_s  = out;                                  // 4096*3
    float* out_feat   = out + S_PTS * 3;                      // 4096*128
    float* out_rf     = out_feat + S_PTS * 128;               // 4096*16*28
    float* out_ni     = out_rf + (size_t)S_PTS * KNN * 28;    // 4096*16

    prep_kernel<<<(N_PTS + 255) / 256, 256>>>(xyz, si, out_xyz_s);
    knn_kernel<<<512, 256>>>(out_ni);                          // 4096 warps, 2 queries each
    rf_adf_kernel<<<528, 256>>>(out_rf, si);
    gemm1_kernel<<<(S_PTS * 64) / 256, 256>>>(Ww, bw, Wb, bb);
    statspw1_kernel<<<32, 256>>>(gw, betaw, gb, betab, feature, si);
    gemm2_kernel<<<(S_PTS * 128) / 256, 256>>>(Wo, bo);
    bnpw2_kernel<<<32, 256>>>(go, betao, out_feat);
}

// round 9
// speedup vs baseline: 9.1548x; 1.1072x over previous
#include <cuda_runtime.h>
#include <math.h>

#define N_PTS 8192
#define S_PTS 4096
#define KNN   16
#define FULLM 0xffffffffu
#define NBB   256          // buckets for before (8192 pts)
#define NBA   128          // buckets for after  (4096 pts)

// ---------------- scratch (__device__ globals; no allocation allowed) ----------------
__device__ float4 g_pts[N_PTS];          // x,y,z,sq original points
__device__ float4 g_pts_s[S_PTS];        // x,y,z,sq sampled points
__device__ float4 g_spts_b[N_PTS];       // x-bucket-sorted before points
__device__ int    g_sidx_b[N_PTS];
__device__ float4 g_spts_a[S_PTS];       // x-bucket-sorted after points
__device__ int    g_sidx_a[S_PTS];
__device__ unsigned g_minmax[4];         // mapped: xmin_b, xmax_b, xmin_a, xmax_a
__device__ int    g_cnt_b[NBB], g_fill_b[NBB], g_off_b[NBB + 1];
__device__ int    g_cnt_a[NBA], g_fill_a[NBA], g_off_a[NBA + 1];
__device__ int    g_ni_after[S_PTS * KNN];
__device__ int4   g_anch_a[S_PTS];       // first 4 after-neighbors (sampled idx)
__device__ int4   g_anch_b[S_PTS];       // first 4 before-neighbors (global idx)
__device__ float  g_intra_a8[S_PTS * 8]; // 6 intra dists, padded to 8
__device__ float  g_intra_b8[S_PTS * 8];
__device__ float  g_adf[S_PTS * 28];
__device__ float  g_y[S_PTS * 128];      // [s][0:64)=yw, [s][64:128)=yb
__device__ float  g_fmT[64 * S_PTS];     // transposed: [ch][s]
__device__ float  g_z[S_PTS * 128];

// ---------------- reference-rounding helpers ----------------
__device__ __forceinline__ float sq_ref(float x, float y, float z) {
    return __fadd_rn(__fadd_rn(__fmul_rn(x, x), __fmul_rn(y, y)), __fmul_rn(z, z));
}
// dot: cuBLAS SGEMM K=3 fma chain, acc0 = rn(x*x'); d2: rn elementwise fusion
__device__ __forceinline__ float d2_ref(float4 a, float4 b) {
    float dot = fmaf(a.z, b.z, fmaf(a.y, b.y, __fmul_rn(a.x, b.x)));
    float d2  = __fsub_rn(__fadd_rn(a.w, b.w), __fmul_rn(2.0f, dot));
    return fmaxf(d2, 0.0f);
}
__device__ __forceinline__ float d_ref(float4 a, float4 b) {
    float d2 = d2_ref(a, b);
    return d2 > 0.0f ? __fsqrt_rn(d2) : 0.0f;
}
__device__ __forceinline__ float leaky(float v) {
    return v >= 0.0f ? v : 0.2f * v;
}
__device__ __forceinline__ unsigned long long mk_key(float d, unsigned idx) {
    return ((unsigned long long)__float_as_uint(d) << 13) | idx;
}
// monotone unsigned mapping of float (for atomic min/max)
__device__ __forceinline__ unsigned fmap(float x) {
    unsigned u = __float_as_uint(x);
    return (u & 0x80000000u) ? ~u : (u | 0x80000000u);
}
__device__ __forceinline__ float funmap(unsigned m) {
    unsigned u = (m & 0x80000000u) ? (m ^ 0x80000000u) : ~m;
    return __uint_as_float(u);
}
__device__ __forceinline__ int bucket_of(float x, float xmin, float scale, int nb) {
    int b = (int)((x - xmin) * scale);
    return min(max(b, 0), nb - 1);
}

// ---------------- init: reset counters + minmax sentinels ----------------
__global__ void init_kernel() {
    int t = threadIdx.x;
    if (t < NBB) { g_cnt_b[t] = 0; g_fill_b[t] = 0; }
    if (t < NBA) { g_cnt_a[t] = 0; g_fill_a[t] = 0; }
    if (t == 0) {
        g_minmax[0] = 0xFFFFFFFFu; g_minmax[1] = 0u;
        g_minmax[2] = 0xFFFFFFFFu; g_minmax[3] = 0u;
    }
}

// ---------------- prep: pack points, gather sampled, emit xyz_s, x min/max ----------------
__global__ void prep_kernel(const float* __restrict__ xyz,
                            const int* __restrict__ si,
                            float* __restrict__ out_xyz_s) {
    int i = blockIdx.x * blockDim.x + threadIdx.x;
    int lane = threadIdx.x & 31;
    if (i < N_PTS) {
        float x = xyz[3 * i], y = xyz[3 * i + 1], z = xyz[3 * i + 2];
        g_pts[i] = make_float4(x, y, z, sq_ref(x, y, z));
        unsigned m = fmap(x);
        unsigned wmin = __reduce_min_sync(FULLM, m);
        unsigned wmax = __reduce_max_sync(FULLM, m);
        if (lane == 0) { atomicMin(&g_minmax[0], wmin); atomicMax(&g_minmax[1], wmax); }
    }
    if (i < S_PTS) {
        int g = si[i];
        float x = xyz[3 * g], y = xyz[3 * g + 1], z = xyz[3 * g + 2];
        g_pts_s[i] = make_float4(x, y, z, sq_ref(x, y, z));
        out_xyz_s[3 * i]     = x;
        out_xyz_s[3 * i + 1] = y;
        out_xyz_s[3 * i + 2] = z;
        unsigned m = fmap(x);
        unsigned wmin = __reduce_min_sync(FULLM, m);
        unsigned wmax = __reduce_max_sync(FULLM, m);
        if (lane == 0) { atomicMin(&g_minmax[2], wmin); atomicMax(&g_minmax[3], wmax); }
    }
}

// ---------------- hist ----------------
__global__ void hist_kernel() {
    int i = blockIdx.x * 256 + threadIdx.x;
    if (i < N_PTS) {
        float xmin = funmap(g_minmax[0]), xmax = funmap(g_minmax[1]);
        float scale = NBB / fmaxf(xmax - xmin, 1e-20f);
        atomicAdd(&g_cnt_b[bucket_of(g_pts[i].x, xmin, scale, NBB)], 1);
    } else {
        int j = i - N_PTS;   // < S_PTS
        float xmin = funmap(g_minmax[2]), xmax = funmap(g_minmax[3]);
        float scale = NBA / fmaxf(xmax - xmin, 1e-20f);
        atomicAdd(&g_cnt_a[bucket_of(g_pts_s[j].x, xmin, scale, NBA)], 1);
    }
}

// ---------------- scan: exclusive prefix sums (Hillis-Steele in smem) ----------------
__global__ void scan_kernel() {
    __shared__ int a[NBB], b[NBB];
    int t = threadIdx.x;
    if (t < NBB) a[t] = g_cnt_b[t];
    __syncthreads();
    int *src = a, *dst = b;
    for (int off = 1; off < NBB; off <<= 1) {
        if (t < NBB) dst[t] = src[t] + ((t >= off) ? src[t - off] : 0);
        __syncthreads();
        int* tmp = src; src = dst; dst = tmp;
    }
    if (t < NBB) g_off_b[t + 1] = src[t];
    if (t == 0) g_off_b[0] = 0;
    __syncthreads();
    if (t < NBA) a[t] = g_cnt_a[t];
    __syncthreads();
    src = a; dst = b;
    for (int off = 1; off < NBA; off <<= 1) {
        if (t < NBA) dst[t] = src[t] + ((t >= off) ? src[t - off] : 0);
        __syncthreads();
        int* tmp = src; src = dst; dst = tmp;
    }
    if (t < NBA) g_off_a[t + 1] = src[t];
    if (t == 0) g_off_a[0] = 0;
}

// ---------------- scatter ----------------
__global__ void scatter_kernel() {
    int i = blockIdx.x * 256 + threadIdx.x;
    if (i < N_PTS) {
        float xmin = funmap(g_minmax[0]), xmax = funmap(g_minmax[1]);
        float scale = NBB / fmaxf(xmax - xmin, 1e-20f);
        int bkt = bucket_of(g_pts[i].x, xmin, scale, NBB);
        int pos = g_off_b[bkt] + atomicAdd(&g_fill_b[bkt], 1);
        g_spts_b[pos] = g_pts[i];
        g_sidx_b[pos] = i;
    } else {
        int j = i - N_PTS;
        float xmin = funmap(g_minmax[2]), xmax = funmap(g_minmax[3]);
        float scale = NBA / fmaxf(xmax - xmin, 1e-20f);
        int bkt = bucket_of(g_pts_s[j].x, xmin, scale, NBA);
        int pos = g_off_a[bkt] + atomicAdd(&g_fill_a[bkt], 1);
        g_spts_a[pos] = g_pts_s[j];
        g_sidx_a[pos] = j;
    }
}

// ---------------- KNN core: lane-distributed sorted top-K ----------------
// key = (f32bits(d) << 13) | idx : integer order == lex (d, idx), tie -> lower index,
// exactly jax.lax.top_k(-D). Selection is order-independent (total comparator), so
// scanning candidates in bucket order is exact.
template <int K>
__device__ __forceinline__ void insert_surv(unsigned bal, unsigned long long nk,
                                            unsigned long long& key, float& thrf, int lane) {
    if (!bal) return;
    do {
        int pl = __ffs(bal) - 1;
        bal &= bal - 1;
        unsigned long long ck = __shfl_sync(FULLM, nk, pl);
        unsigned lt = __ballot_sync(FULLM, ck < key);
        int pos = __ffs(lt) - 1;              // uniform across warp
        if (pos >= 0 && pos < K) {
            unsigned long long up = __shfl_up_sync(FULLM, key, 1);
            if (lane == pos)      key = ck;
            else if (lane > pos)  key = up;
            if (lane >= K)        key = ~0ull;
        }
    } while (bal);
    unsigned long long kth = __shfl_sync(FULLM, key, K - 1);
    if (kth != ~0ull) {                       // K-th slot real -> tighten threshold
        float dk = __uint_as_float((unsigned)(kth >> 13));
        thrf = fmaf(dk, dk, 1e-3f);           // conservative fma-domain superset
    }
}

template <int K>
__device__ __forceinline__ void scan_range(int s, int e, float4 qp,
                                           const float4* __restrict__ spts,
                                           const int* __restrict__ sidx, int lane,
                                           unsigned long long& key, float& thr) {
    for (int t = s; t < e; t += 32) {
        int j = t + lane;
        bool in = j < e;
        float4 cp = in ? spts[j] : make_float4(1e30f, 1e30f, 1e30f, 1e30f);
        int id = in ? sidx[j] : 0;
        float dot = fmaf(qp.z, cp.z, fmaf(qp.y, cp.y, qp.x * cp.x));
        float d2f = fmaf(-2.0f, dot, qp.w + cp.w);
        bool surv = in && (d2f < thr);
        unsigned long long nk = ~0ull;
        if (surv) nk = mk_key(d_ref(qp, cp), (unsigned)id);   // exact reference math
        unsigned bal = __ballot_sync(FULLM, surv);
        insert_surv<K>(bal, nk, key, thr, lane);
    }
}

template <int K, bool AFTER>
__device__ __forceinline__ void emit_knn(unsigned long long key, int q, int lane,
                                         const float4* __restrict__ cand,
                                         float* __restrict__ out_ni_f) {
    int idx = (int)(key & 0x1FFFu);
    if (AFTER && lane < K) {
        g_ni_after[q * KNN + lane] = idx;
        out_ni_f[q * KNN + lane]   = (float)idx;
    }
    unsigned long long k1 = __shfl_sync(FULLM, key, 1);
    unsigned long long k2 = __shfl_sync(FULLM, key, 2);
    unsigned long long k3 = __shfl_sync(FULLM, key, 3);
    if (lane == 0) {
        int i1 = (int)(k1 & 0x1FFF), i2 = (int)(k2 & 0x1FFF), i3 = (int)(k3 & 0x1FFF);
        float d1  = __uint_as_float((unsigned)(k1 >> 13));
        float d2v = __uint_as_float((unsigned)(k2 >> 13));
        float d3  = __uint_as_float((unsigned)(k3 >> 13));
        float4 A1 = cand[i1], A2 = cand[i2], A3 = cand[i3];
        float* intra = AFTER ? (g_intra_a8 + q * 8) : (g_intra_b8 + q * 8);
        *(float4*)intra       = make_float4(d1, d2v, d3, d_ref(A1, A2));
        *(float4*)(intra + 4) = make_float4(d_ref(A1, A3), d_ref(A2, A3), 0.0f, 0.0f);
        if (AFTER) g_anch_a[q] = make_int4(idx, i1, i2, i3);
        else       g_anch_b[q] = make_int4(idx, i1, i2, i3);
    }
}

// warp-per-query bucketed sweep: process own bucket, expand outward, prune by edge bound.
// Any pruned candidate has d_exact >= edge_dist > sqrt(thr) >= d_K -> provably not top-K.
template <int K, int NB, bool AFTER>
__device__ __forceinline__ void knn_bucket_warp(int q, int lane, float* __restrict__ out_ni_f) {
    const float4* __restrict__ spts = AFTER ? g_spts_a : g_spts_b;
    const int*   __restrict__ sidx  = AFTER ? g_sidx_a : g_sidx_b;
    const int*   __restrict__ off   = AFTER ? g_off_a  : g_off_b;
    const float4* __restrict__ cand = AFTER ? g_pts_s  : g_pts;
    float xmin = funmap(g_minmax[AFTER ? 2 : 0]);
    float xmax = funmap(g_minmax[AFTER ? 3 : 1]);
    float scale = NB / fmaxf(xmax - xmin, 1e-20f);
    float width = (xmax - xmin) / NB;
    float4 qp = g_pts_s[q];

    unsigned long long key = ~0ull;
    float thr = 3.4e38f;

    int qb = bucket_of(qp.x, xmin, scale, NB);
    scan_range<K>(off[qb], off[qb + 1], qp, spts, sidx, lane, key, thr);
    int bl = qb - 1, br = qb + 1;
    while (true) {
        float dl = 1e30f, dr = 1e30f;
        if (bl >= 0) dl = fmaxf(0.0f, qp.x - (xmin + (bl + 1) * width) - 1e-3f);
        if (br < NB) dr = fmaxf(0.0f, (xmin + br * width) - qp.x - 1e-3f);
        bool okl = (bl >= 0) && (dl * dl < thr);
        bool okr = (br < NB) && (dr * dr < thr);
        if (!okl && !okr) break;
        if (okl && (!okr || dl <= dr)) {
            scan_range<K>(off[bl], off[bl + 1], qp, spts, sidx, lane, key, thr);
            bl--;
        } else {
            scan_range<K>(off[br], off[br + 1], qp, spts, sidx, lane, key, thr);
            br++;
        }
    }
    emit_knn<K, AFTER>(key, q, lane, cand, out_ni_f);
}

__global__ void __launch_bounds__(256) knn_kernel(float* __restrict__ out_ni_f) {
    int gw   = blockIdx.x * 8 + (threadIdx.x >> 5);   // 8192 warps
    int lane = threadIdx.x & 31;
    if (gw < S_PTS) knn_bucket_warp<KNN, NBA, true >(gw, lane, out_ni_f);
    else            knn_bucket_warp<4,   NBB, false>(gw - S_PTS, lane, out_ni_f);
}

// ---------------- fused rf (512 blocks, 2 threads/row) + adf (16 blocks) ----------------
__global__ void __launch_bounds__(256) rf_adf_kernel(float* __restrict__ out_rf,
                                                     const int* __restrict__ si) {
    int b = blockIdx.x;
    if (b < 512) {
        int id = b * 256 + threadIdx.x;           // < 131072
        int i = id >> 1, h = id & 1;              // row, half
        int n = i >> 4, k = i & 15;
        int nb = g_ni_after[n * KNN + k];
        int4 an  = g_anch_a[n];
        int4 anb = g_anch_a[nb];
        float4 Q0 = g_pts_s[anb.x], Q1 = g_pts_s[anb.y], Q2 = g_pts_s[anb.z], Q3 = g_pts_s[anb.w];
        float* o = out_rf + (size_t)i * 28;
        if (h == 0) {
            float4 a0 = *(const float4*)(g_intra_a8 + n * 8);
            float4 a1 = *(const float4*)(g_intra_a8 + n * 8 + 4);
            float4 c0 = *(const float4*)(g_intra_a8 + nb * 8);
            float4 c1 = *(const float4*)(g_intra_a8 + nb * 8 + 4);
            float4 P0 = g_pts_s[an.x], P1 = g_pts_s[an.y];
            ((float4*)o)[0] = make_float4(a0.x, a0.y, a0.z, a0.w);
            ((float4*)o)[1] = make_float4(a1.x, a1.y, c0.x, c0.y);
            ((float4*)o)[2] = make_float4(c0.z, c0.w, c1.x, c1.y);
            ((float4*)o)[3] = make_float4(d_ref(P0,Q0), d_ref(P0,Q1), d_ref(P0,Q2), d_ref(P0,Q3));
            ((float4*)o)[4] = make_float4(d_ref(P1,Q0), d_ref(P1,Q1), d_ref(P1,Q2), d_ref(P1,Q3));
        } else {
            float4 P2 = g_pts_s[an.z], P3 = g_pts_s[an.w];
            ((float4*)o)[5] = make_float4(d_ref(P2,Q0), d_ref(P2,Q1), d_ref(P2,Q2), d_ref(P2,Q3));
            ((float4*)o)[6] = make_float4(d_ref(P3,Q0), d_ref(P3,Q1), d_ref(P3,Q2), d_ref(P3,Q3));
        }
    } else {
        int s = (b - 512) * 256 + threadIdx.x;    // < 4096
        float4 b0 = *(const float4*)(g_intra_b8 + s * 8);
        float4 b1 = *(const float4*)(g_intra_b8 + s * 8 + 4);
        float4 a0 = *(const float4*)(g_intra_a8 + s * 8);
        float4 a1 = *(const float4*)(g_intra_a8 + s * 8 + 4);
        int4 ab = g_anch_b[s];
        int4 aa = g_anch_a[s];
        float4 P0 = g_pts[ab.x], P1 = g_pts[ab.y], P2 = g_pts[ab.z], P3 = g_pts[ab.w];
        float4 Q0 = g_pts[si[aa.x]], Q1 = g_pts[si[aa.y]], Q2 = g_pts[si[aa.z]], Q3 = g_pts[si[aa.w]];
        float* o = g_adf + s * 28;
        ((float4*)o)[0] = make_float4(b0.x, b0.y, b0.z, b0.w);
        ((float4*)o)[1] = make_float4(b1.x, b1.y, a0.x, a0.y);
        ((float4*)o)[2] = make_float4(a0.z, a0.w, a1.x, a1.y);
        ((float4*)o)[3] = make_float4(d_ref(P0,Q0), d_ref(P0,Q1), d_ref(P0,Q2), d_ref(P0,Q3));
        ((float4*)o)[4] = make_float4(d_ref(P1,Q0), d_ref(P1,Q1), d_ref(P1,Q2), d_ref(P1,Q3));
        ((float4*)o)[5] = make_float4(d_ref(P2,Q0), d_ref(P2,Q1), d_ref(P2,Q2), d_ref(P2,Q3));
        ((float4*)o)[6] = make_float4(d_ref(P3,Q0), d_ref(P3,Q1), d_ref(P3,Q2), d_ref(P3,Q3));
    }
}

// ---------------- gemm1: y = adf @ {Ww|Wb} + {bw|bb}, thread per (s,ch) ----------------
__global__ void __launch_bounds__(256) gemm1_kernel(
    const float* __restrict__ Ww, const float* __restrict__ bw,
    const float* __restrict__ Wb, const float* __restrict__ bb) {
    int tid = blockIdx.x * blockDim.x + threadIdx.x;
    int ch = tid & 63, s = tid >> 6;
    float aw = bw[ch], ab = bb[ch];
    const float* a = g_adf + s * 28;
#pragma unroll
    for (int c = 0; c < 28; c++) {
        float av = a[c];
        aw = fmaf(av, Ww[c * 64 + ch], aw);
        ab = fmaf(av, Wb[c * 64 + ch], ab);
    }
    g_y[s * 128 + ch]      = aw;
    g_y[s * 128 + 64 + ch] = ab;
}

// ---------------- statspw1: BN stats (w & b) + gate + leaky, 2 channels/block ----------------
__global__ void __launch_bounds__(256) statspw1_kernel(
    const float* __restrict__ gw, const float* __restrict__ betaw,
    const float* __restrict__ gb, const float* __restrict__ betab,
    const float* __restrict__ feature, const int* __restrict__ si) {
    __shared__ float2 red[256], red2[256];
    __shared__ float  stats[8];
    int ch2 = blockIdx.x * 2, tid = threadIdx.x;
    float2 vw[16], vb[16];
    float2 sw = make_float2(0.f, 0.f), s2w = make_float2(0.f, 0.f);
    float2 sb = make_float2(0.f, 0.f), s2b = make_float2(0.f, 0.f);
#pragma unroll
    for (int i = 0; i < 16; i++) {
        int r = i * 256 + tid;
        float2 w = *(const float2*)(g_y + (size_t)r * 128 + ch2);
        float2 b = *(const float2*)(g_y + (size_t)r * 128 + 64 + ch2);
        vw[i] = w; vb[i] = b;
        sw.x += w.x; sw.y += w.y; s2w.x = fmaf(w.x, w.x, s2w.x); s2w.y = fmaf(w.y, w.y, s2w.y);
        sb.x += b.x; sb.y += b.y; s2b.x = fmaf(b.x, b.x, s2b.x); s2b.y = fmaf(b.y, b.y, s2b.y);
    }
    red[tid] = sw; red2[tid] = s2w; __syncthreads();
    for (int st = 128; st > 0; st >>= 1) {
        if (tid < st) {
            red[tid].x += red[tid + st].x;  red[tid].y += red[tid + st].y;
            red2[tid].x += red2[tid + st].x; red2[tid].y += red2[tid + st].y;
        }
        __syncthreads();
    }
    if (tid == 0) {
        float mu0 = red[0].x / (float)S_PTS, mu1 = red[0].y / (float)S_PTS;
        stats[0] = mu0; stats[1] = mu1;
        stats[2] = rsqrtf(red2[0].x / (float)S_PTS - mu0 * mu0 + 1e-5f);
        stats[3] = rsqrtf(red2[0].y / (float)S_PTS - mu1 * mu1 + 1e-5f);
    }
    __syncthreads();
    red[tid] = sb; red2[tid] = s2b; __syncthreads();
    for (int st = 128; st > 0; st >>= 1) {
        if (tid < st) {
            red[tid].x += red[tid + st].x;  red[tid].y += red[tid + st].y;
            red2[tid].x += red2[tid + st].x; red2[tid].y += red2[tid + st].y;
        }
        __syncthreads();
    }
    if (tid == 0) {
        float mu0 = red[0].x / (float)S_PTS, mu1 = red[0].y / (float)S_PTS;
        stats[4] = mu0; stats[5] = mu1;
        stats[6] = rsqrtf(red2[0].x / (float)S_PTS - mu0 * mu0 + 1e-5f);
        stats[7] = rsqrtf(red2[0].y / (float)S_PTS - mu1 * mu1 + 1e-5f);
    }
    __syncthreads();
    float muw0 = stats[0], muw1 = stats[1], rsw0 = stats[2], rsw1 = stats[3];
    float mub0 = stats[4], mub1 = stats[5], rsb0 = stats[6], rsb1 = stats[7];
    float gw0 = gw[ch2], gw1 = gw[ch2 + 1], bew0 = betaw[ch2], bew1 = betaw[ch2 + 1];
    float gb0 = gb[ch2], gb1 = gb[ch2 + 1], beb0 = betab[ch2], beb1 = betab[ch2 + 1];
#pragma unroll
    for (int i = 0; i < 16; i++) {
        int r = i * 256 + tid;
        float2 f = *(const float2*)(feature + (size_t)si[r] * 64 + ch2);
        float w0 = (vw[i].x - muw0) * rsw0 * gw0 + bew0;
        float w1 = (vw[i].y - muw1) * rsw1 * gw1 + bew1;
        float b0 = (vb[i].x - mub0) * rsb0 * gb0 + beb0;
        float b1 = (vb[i].y - mub1) * rsb1 * gb1 + beb1;
        g_fmT[(size_t)ch2 * S_PTS + r]       = leaky(fmaf(f.x, w0, b0));
        g_fmT[(size_t)(ch2 + 1) * S_PTS + r] = leaky(fmaf(f.y, w1, b1));
    }
}

// ---------------- GEMM2: z = [fm | adf] @ Wo + bo ----------------
__global__ void gemm2_kernel(const float* __restrict__ Wo, const float* __restrict__ bo) {
    int tid = blockIdx.x * blockDim.x + threadIdx.x;
    int ch = tid & 127, s = tid >> 7;
    if (s >= S_PTS) return;
    float acc = bo[ch];
#pragma unroll
    for (int c = 0; c < 64; c++) acc = fmaf(g_fmT[c * S_PTS + s], Wo[c * 128 + ch], acc);
    const float* a = g_adf + s * 28;
#pragma unroll
    for (int c = 0; c < 28; c++) acc = fmaf(a[c], Wo[(64 + c) * 128 + ch], acc);
    g_z[s * 128 + ch] = acc;
}

// ---------------- bnpw2: BN stats + affine + leaky, 4 channels/block, float4 I/O ----------------
__global__ void __launch_bounds__(256) bnpw2_kernel(const float* __restrict__ go,
                                                    const float* __restrict__ betao,
                                                    float* __restrict__ out_feat) {
    __shared__ float4 red[256], red2[256];
    __shared__ float4 stats[2];
    int ch4 = blockIdx.x * 4, tid = threadIdx.x;
    float4 v[16];
    float4 s  = make_float4(0.f, 0.f, 0.f, 0.f);
    float4 s2 = make_float4(0.f, 0.f, 0.f, 0.f);
#pragma unroll
    for (int i = 0; i < 16; i++) {
        int r = i * 256 + tid;
        float4 val = *(const float4*)(g_z + (size_t)r * 128 + ch4);
        v[i] = val;
        s.x += val.x; s.y += val.y; s.z += val.z; s.w += val.w;
        s2.x = fmaf(val.x, val.x, s2.x); s2.y = fmaf(val.y, val.y, s2.y);
        s2.z = fmaf(val.z, val.z, s2.z); s2.w = fmaf(val.w, val.w, s2.w);
    }
    red[tid] = s; red2[tid] = s2;
    __syncthreads();
    for (int st = 128; st > 0; st >>= 1) {
        if (tid < st) {
            float4 a = red[tid + st], a2 = red2[tid + st];
            red[tid].x += a.x; red[tid].y += a.y; red[tid].z += a.z; red[tid].w += a.w;
            red2[tid].x += a2.x; red2[tid].y += a2.y; red2[tid].z += a2.z; red2[tid].w += a2.w;
        }
        __syncthreads();
    }
    if (tid == 0) {
        float4 sum = red[0], sum2 = red2[0];
        float4 mu = make_float4(sum.x / S_PTS, sum.y / S_PTS, sum.z / S_PTS, sum.w / S_PTS);
        stats[0] = mu;
        stats[1] = make_float4(rsqrtf(sum2.x / S_PTS - mu.x * mu.x + 1e-5f),
                               rsqrtf(sum2.y / S_PTS - mu.y * mu.y + 1e-5f),
                               rsqrtf(sum2.z / S_PTS - mu.z * mu.z + 1e-5f),
                               rsqrtf(sum2.w / S_PTS - mu.w * mu.w + 1e-5f));
    }
    __syncthreads();
    float4 mu = stats[0], rs = stats[1];
    float4 g  = *(const float4*)(go + ch4);
    float4 be = *(const float4*)(betao + ch4);
#pragma unroll
    for (int i = 0; i < 16; i++) {
        int r = i * 256 + tid;
        float4 val = v[i];
        float4 o;
        o.x = leaky((val.x - mu.x) * rs.x * g.x + be.x);
        o.y = leaky((val.y - mu.y) * rs.y * g.y + be.y);
        o.z = leaky((val.z - mu.z) * rs.z * g.z + be.z);
        o.w = leaky((val.w - mu.w) * rs.w * g.w + be.w);
        *(float4*)(out_feat + (size_t)r * 128 + ch4) = o;
    }
}

// ---------------- launch ----------------
extern "C" void kernel_launch(void* const* d_in, const int* in_sizes, int n_in,
                              void* d_out, int out_size) {
    const float* xyz     = (const float*)d_in[0];
    const float* feature = (const float*)d_in[1];
    const int*   si      = (const int*)  d_in[2];
    const float* Ww    = (const float*)d_in[3];
    const float* bw    = (const float*)d_in[4];
    const float* gw    = (const float*)d_in[5];
    const float* betaw = (const float*)d_in[6];
    const float* Wb    = (const float*)d_in[7];
    const float* bb    = (const float*)d_in[8];
    const float* gb    = (const float*)d_in[9];
    const float* betab = (const float*)d_in[10];
    const float* Wo    = (const float*)d_in[11];
    const float* bo    = (const float*)d_in[12];
    const float* go    = (const float*)d_in[13];
    const float* betao = (const float*)d_in[14];

    float* out        = (float*)d_out;
    float* out_xyz_s  = out;                                  // 4096*3
    float* out_feat   = out + S_PTS * 3;                      // 4096*128
    float* out_rf     = out_feat + S_PTS * 128;               // 4096*16*28
    float* out_ni     = out_rf + (size_t)S_PTS * KNN * 28;    // 4096*16

    init_kernel<<<1, 256>>>();
    prep_kernel<<<(N_PTS + 255) / 256, 256>>>(xyz, si, out_xyz_s);
    hist_kernel<<<(N_PTS + S_PTS) / 256, 256>>>();
    scan_kernel<<<1, 256>>>();
    scatter_kernel<<<(N_PTS + S_PTS) / 256, 256>>>();
    knn_kernel<<<1024, 256>>>(out_ni);                         // 8192 warps, 1 query each
    rf_adf_kernel<<<528, 256>>>(out_rf, si);
    gemm1_kernel<<<(S_PTS * 64) / 256, 256>>>(Ww, bw, Wb, bb);
    statspw1_kernel<<<32, 256>>>(gw, betaw, gb, betab, feature, si);
    gemm2_kernel<<<(S_PTS * 128) / 256, 256>>>(Wo, bo);
    bnpw2_kernel<<<32, 256>>>(go, betao, out_feat);
}

// round 10
// speedup vs baseline: 9.9585x; 1.0878x over previous
#include <cuda_runtime.h>
#include <math.h>

#define N_PTS 8192
#define S_PTS 4096
#define KNN   16
#define FULLM 0xffffffffu
#define NBB   512          // buckets for before (8192 pts)
#define NBA   256          // buckets for after  (4096 pts)
#define XMIN_F (-8.0f)     // fixed bucket range (clamp-safe pruning)
#define XRANGE 16.0f

// ---------------- scratch (__device__ globals; zero-initialized at load) ----------------
__device__ float4 g_pts[N_PTS];          // x,y,z,sq original points
__device__ float4 g_pts_s[S_PTS];        // x,y,z,sq sampled points
__device__ float4 g_spts_b[N_PTS];       // x-bucket-sorted before points
__device__ int    g_sidx_b[N_PTS];
__device__ float4 g_spts_a[S_PTS];       // x-bucket-sorted after points
__device__ int    g_sidx_a[S_PTS];
__device__ int    g_cnt_b[NBB], g_fill_b[NBB], g_off_b[NBB + 1];
__device__ int    g_cnt_a[NBA], g_fill_a[NBA], g_off_a[NBA + 1];
__device__ int    g_ni_after[S_PTS * KNN];
__device__ int4   g_anch_a[S_PTS];       // first 4 after-neighbors (sampled idx)
__device__ int4   g_anch_b[S_PTS];       // first 4 before-neighbors (global idx)
__device__ float  g_intra_a8[S_PTS * 8]; // 6 intra dists, padded to 8
__device__ float  g_intra_b8[S_PTS * 8];
__device__ float  g_adf[S_PTS * 28];
__device__ float  g_y[S_PTS * 128];      // [s][0:64)=yw, [s][64:128)=yb
__device__ float  g_fmT[64 * S_PTS];     // transposed: [ch][s]
__device__ float  g_z[S_PTS * 128];

// ---------------- reference-rounding helpers ----------------
__device__ __forceinline__ float sq_ref(float x, float y, float z) {
    return __fadd_rn(__fadd_rn(__fmul_rn(x, x), __fmul_rn(y, y)), __fmul_rn(z, z));
}
// dot: cuBLAS SGEMM K=3 fma chain, acc0 = rn(x*x'); d2: rn elementwise fusion
__device__ __forceinline__ float d2_ref(float4 a, float4 b) {
    float dot = fmaf(a.z, b.z, fmaf(a.y, b.y, __fmul_rn(a.x, b.x)));
    float d2  = __fsub_rn(__fadd_rn(a.w, b.w), __fmul_rn(2.0f, dot));
    return fmaxf(d2, 0.0f);
}
__device__ __forceinline__ float d_ref(float4 a, float4 b) {
    float d2 = d2_ref(a, b);
    return d2 > 0.0f ? __fsqrt_rn(d2) : 0.0f;
}
__device__ __forceinline__ float leaky(float v) {
    return v >= 0.0f ? v : 0.2f * v;
}
__device__ __forceinline__ unsigned long long mk_key(float d, unsigned idx) {
    return ((unsigned long long)__float_as_uint(d) << 13) | idx;
}
__device__ __forceinline__ unsigned long long kmin64(unsigned long long a, unsigned long long b) {
    return a < b ? a : b;
}
__device__ __forceinline__ unsigned long long kmax64(unsigned long long a, unsigned long long b) {
    return a > b ? a : b;
}
__device__ __forceinline__ int bucket_of(float x, int nb) {
    int b = (int)((x - XMIN_F) * ((float)nb / XRANGE));
    return min(max(b, 0), nb - 1);
}
__device__ __forceinline__ unsigned long long bitonic32(unsigned long long key, int lane) {
#pragma unroll
    for (int k = 2; k <= 32; k <<= 1) {
#pragma unroll
        for (int j = k >> 1; j > 0; j >>= 1) {
            unsigned long long other = __shfl_xor_sync(FULLM, key, j);
            bool takemin = (((lane & k) == 0) == ((lane & j) == 0));
            key = takemin ? kmin64(key, other) : kmax64(key, other);
        }
    }
    return key;
}

// ---------------- prep + hist: pack points, gather sampled, emit xyz_s, histogram ----------------
// g_cnt_* are zero at entry (load-time zero for call 0; scan re-zeroes for later calls).
__global__ void prep_kernel(const float* __restrict__ xyz,
                            const int* __restrict__ si,
                            float* __restrict__ out_xyz_s) {
    int i = blockIdx.x * blockDim.x + threadIdx.x;
    if (i < N_PTS) {
        float x = xyz[3 * i], y = xyz[3 * i + 1], z = xyz[3 * i + 2];
        g_pts[i] = make_float4(x, y, z, sq_ref(x, y, z));
        atomicAdd(&g_cnt_b[bucket_of(x, NBB)], 1);
    }
    if (i < S_PTS) {
        int g = si[i];
        float x = xyz[3 * g], y = xyz[3 * g + 1], z = xyz[3 * g + 2];
        g_pts_s[i] = make_float4(x, y, z, sq_ref(x, y, z));
        out_xyz_s[3 * i]     = x;
        out_xyz_s[3 * i + 1] = y;
        out_xyz_s[3 * i + 2] = z;
        atomicAdd(&g_cnt_a[bucket_of(x, NBA)], 1);
    }
}

// ---------------- scan: prefix sums + self-rezero cnt + zero fill ----------------
__global__ void scan_kernel() {
    __shared__ int a[NBB], b[NBB];
    int t = threadIdx.x;                  // 512 threads
    a[t] = g_cnt_b[t];
    __syncthreads();
    int *src = a, *dst = b;
    for (int off = 1; off < NBB; off <<= 1) {
        dst[t] = src[t] + ((t >= off) ? src[t - off] : 0);
        __syncthreads();
        int* tmp = src; src = dst; dst = tmp;
    }
    g_off_b[t + 1] = src[t];
    if (t == 0) g_off_b[0] = 0;
    g_cnt_b[t] = 0;                       // re-zero for next call's prep
    g_fill_b[t] = 0;                      // zero for this call's scatter
    __syncthreads();
    a[t] = (t < NBA) ? g_cnt_a[t] : 0;
    __syncthreads();
    src = a; dst = b;
    for (int off = 1; off < NBA; off <<= 1) {
        dst[t] = src[t] + ((t >= off) ? src[t - off] : 0);
        __syncthreads();
        int* tmp = src; src = dst; dst = tmp;
    }
    if (t < NBA) {
        g_off_a[t + 1] = src[t];
        g_cnt_a[t] = 0;
        g_fill_a[t] = 0;
    }
    if (t == 0) g_off_a[0] = 0;
}

// ---------------- scatter ----------------
__global__ void scatter_kernel() {
    int i = blockIdx.x * 256 + threadIdx.x;
    if (i < N_PTS) {
        int bkt = bucket_of(g_pts[i].x, NBB);
        int pos = g_off_b[bkt] + atomicAdd(&g_fill_b[bkt], 1);
        g_spts_b[pos] = g_pts[i];
        g_sidx_b[pos] = i;
    } else {
        int j = i - N_PTS;
        int bkt = bucket_of(g_pts_s[j].x, NBA);
        int pos = g_off_a[bkt] + atomicAdd(&g_fill_a[bkt], 1);
        g_spts_a[pos] = g_pts_s[j];
        g_sidx_a[pos] = j;
    }
}

// ---------------- KNN core: lane-distributed sorted top-K ----------------
// key = (f32bits(d) << 13) | idx : integer order == lex (d, idx), tie -> lower index,
// exactly jax.lax.top_k(-D). Order-independent total comparator => bucket order exact.
template <int K>
__device__ __forceinline__ void insert_surv(unsigned bal, unsigned long long nk,
                                            unsigned long long& key, float& thrf, int lane) {
    if (!bal) return;
    do {
        int pl = __ffs(bal) - 1;
        bal &= bal - 1;
        unsigned long long ck = __shfl_sync(FULLM, nk, pl);
        unsigned lt = __ballot_sync(FULLM, ck < key);
        int pos = __ffs(lt) - 1;              // uniform across warp
        if (pos >= 0 && pos < K) {
            unsigned long long up = __shfl_up_sync(FULLM, key, 1);
            if (lane == pos)      key = ck;
            else if (lane > pos)  key = up;
            if (lane >= K)        key = ~0ull;
        }
    } while (bal);
    unsigned long long kth = __shfl_sync(FULLM, key, K - 1);
    if (kth != ~0ull) {                       // K-th slot real -> tighten threshold
        float dk = __uint_as_float((unsigned)(kth >> 13));
        thrf = fmaf(dk, dk, 1e-3f);           // conservative fma-domain superset
    }
}

template <int K>
__device__ __forceinline__ void scan_range(int s, int e, float4 qp,
                                           const float4* __restrict__ spts,
                                           const int* __restrict__ sidx, int lane,
                                           unsigned long long& key, float& thr) {
    for (int t = s; t < e; t += 32) {
        int j = t + lane;
        bool in = j < e;
        float4 cp = in ? spts[j] : make_float4(1e30f, 1e30f, 1e30f, 1e30f);
        int id = in ? sidx[j] : 0;
        float dot = fmaf(qp.z, cp.z, fmaf(qp.y, cp.y, qp.x * cp.x));
        float d2f = fmaf(-2.0f, dot, qp.w + cp.w);
        bool surv = in && (d2f < thr);
        unsigned long long nk = ~0ull;
        if (surv) nk = mk_key(d_ref(qp, cp), (unsigned)id);   // exact reference math
        unsigned bal = __ballot_sync(FULLM, surv);
        insert_surv<K>(bal, nk, key, thr, lane);
    }
}

template <int K, bool AFTER>
__device__ __forceinline__ void emit_knn(unsigned long long key, int q, int lane,
                                         const float4* __restrict__ cand,
                                         float* __restrict__ out_ni_f) {
    int idx = (int)(key & 0x1FFFu);
    if (AFTER && lane < K) {
        g_ni_after[q * KNN + lane] = idx;
        out_ni_f[q * KNN + lane]   = (float)idx;
    }
    unsigned long long k1 = __shfl_sync(FULLM, key, 1);
    unsigned long long k2 = __shfl_sync(FULLM, key, 2);
    unsigned long long k3 = __shfl_sync(FULLM, key, 3);
    if (lane == 0) {
        int i1 = (int)(k1 & 0x1FFF), i2 = (int)(k2 & 0x1FFF), i3 = (int)(k3 & 0x1FFF);
        float d1  = __uint_as_float((unsigned)(k1 >> 13));
        float d2v = __uint_as_float((unsigned)(k2 >> 13));
        float d3  = __uint_as_float((unsigned)(k3 >> 13));
        float4 A1 = cand[i1], A2 = cand[i2], A3 = cand[i3];
        float* intra = AFTER ? (g_intra_a8 + q * 8) : (g_intra_b8 + q * 8);
        *(float4*)intra       = make_float4(d1, d2v, d3, d_ref(A1, A2));
        *(float4*)(intra + 4) = make_float4(d_ref(A1, A3), d_ref(A2, A3), 0.0f, 0.0f);
        if (AFTER) g_anch_a[q] = make_int4(idx, i1, i2, i3);
        else       g_anch_b[q] = make_int4(idx, i1, i2, i3);
    }
}

// warp-per-query bucketed sweep with bitonic seed of own bucket's first 32 candidates.
// Seed ranks >= K are dominated by ranks < K (provably never top-K). Pruned buckets
// have edge_dist > sqrt(thr) >= d_K -> provably not top-K.
template <int K, int NB, bool AFTER>
__device__ __forceinline__ void knn_bucket_warp(int q, int lane, float* __restrict__ out_ni_f) {
    const float4* __restrict__ spts = AFTER ? g_spts_a : g_spts_b;
    const int*   __restrict__ sidx  = AFTER ? g_sidx_a : g_sidx_b;
    const int*   __restrict__ off   = AFTER ? g_off_a  : g_off_b;
    const float4* __restrict__ cand = AFTER ? g_pts_s  : g_pts;
    const float width = XRANGE / NB;
    float4 qp = g_pts_s[q];

    int qb = bucket_of(qp.x, NB);
    int s0 = off[qb], e0 = off[qb + 1];

    // seed: bitonic-sort exact keys of first min(32, bucket size) candidates
    int j = s0 + lane;
    bool v = j < e0;
    float4 c0 = v ? spts[j] : make_float4(1e30f, 1e30f, 1e30f, 1e30f);
    unsigned long long key = v ? mk_key(d_ref(qp, c0), (unsigned)sidx[j]) : ~0ull;
    key = bitonic32(key, lane);
    if (lane >= K) key = ~0ull;
    float thr = 3.4e38f;
    {
        unsigned long long kth = __shfl_sync(FULLM, key, K - 1);
        if (kth != ~0ull) {
            float dk = __uint_as_float((unsigned)(kth >> 13));
            thr = fmaf(dk, dk, 1e-3f);
        }
    }
    // rest of own bucket (if > 32 candidates)
    scan_range<K>(s0 + 32, e0, qp, spts, sidx, lane, key, thr);

    int bl = qb - 1, br = qb + 1;
    while (true) {
        float dl = 1e30f, dr = 1e30f;
        if (bl >= 0) dl = fmaxf(0.0f, qp.x - (XMIN_F + (bl + 1) * width) - 1e-3f);
        if (br < NB) dr = fmaxf(0.0f, (XMIN_F + br * width) - qp.x - 1e-3f);
        bool okl = (bl >= 0) && (dl * dl < thr);
        bool okr = (br < NB) && (dr * dr < thr);
        if (!okl && !okr) break;
        if (okl && (!okr || dl <= dr)) {
            scan_range<K>(off[bl], off[bl + 1], qp, spts, sidx, lane, key, thr);
            bl--;
        } else {
            scan_range<K>(off[br], off[br + 1], qp, spts, sidx, lane, key, thr);
            br++;
        }
    }
    emit_knn<K, AFTER>(key, q, lane, cand, out_ni_f);
}

__global__ void __launch_bounds__(256) knn_kernel(float* __restrict__ out_ni_f) {
    int gw   = blockIdx.x * 8 + (threadIdx.x >> 5);   // 8192 warps
    int lane = threadIdx.x & 31;
    if (gw < S_PTS) knn_bucket_warp<KNN, NBA, true >(gw, lane, out_ni_f);
    else            knn_bucket_warp<4,   NBB, false>(gw - S_PTS, lane, out_ni_f);
}

// ---------------- fused rf (1024 blocks, 4 threads/row) + adf (16 blocks) ----------------
__global__ void __launch_bounds__(256) rf_adf_kernel(float* __restrict__ out_rf,
                                                     const int* __restrict__ si) {
    int b = blockIdx.x;
    if (b < 1024) {
        int id = b * 256 + threadIdx.x;           // < 262144
        int i = id >> 2, h = id & 3;              // row, quarter
        int n = i >> 4, k = i & 15;
        int nb = g_ni_after[n * KNN + k];
        int4 an  = g_anch_a[n];
        int4 anb = g_anch_a[nb];
        float4 Q0 = g_pts_s[anb.x], Q1 = g_pts_s[anb.y], Q2 = g_pts_s[anb.z], Q3 = g_pts_s[anb.w];
        float* o = out_rf + (size_t)i * 28;
        float4 P;
        if (h == 0) {
            float4 a0 = *(const float4*)(g_intra_a8 + n * 8);
            float4 a1 = *(const float4*)(g_intra_a8 + n * 8 + 4);
            float4 c0 = *(const float4*)(g_intra_a8 + nb * 8);
            float4 c1 = *(const float4*)(g_intra_a8 + nb * 8 + 4);
            ((float4*)o)[0] = make_float4(a0.x, a0.y, a0.z, a0.w);
            ((float4*)o)[1] = make_float4(a1.x, a1.y, c0.x, c0.y);
            ((float4*)o)[2] = make_float4(c0.z, c0.w, c1.x, c1.y);
            P = g_pts_s[an.x];
        } else if (h == 1) P = g_pts_s[an.y];
        else if (h == 2)   P = g_pts_s[an.z];
        else               P = g_pts_s[an.w];
        ((float4*)o)[3 + h] = make_float4(d_ref(P,Q0), d_ref(P,Q1), d_ref(P,Q2), d_ref(P,Q3));
    } else {
        int s = (b - 1024) * 256 + threadIdx.x;   // < 4096
        float4 b0 = *(const float4*)(g_intra_b8 + s * 8);
        float4 b1 = *(const float4*)(g_intra_b8 + s * 8 + 4);
        float4 a0 = *(const float4*)(g_intra_a8 + s * 8);
        float4 a1 = *(const float4*)(g_intra_a8 + s * 8 + 4);
        int4 ab = g_anch_b[s];
        int4 aa = g_anch_a[s];
        float4 P0 = g_pts[ab.x], P1 = g_pts[ab.y], P2 = g_pts[ab.z], P3 = g_pts[ab.w];
        float4 Q0 = g_pts[si[aa.x]], Q1 = g_pts[si[aa.y]], Q2 = g_pts[si[aa.z]], Q3 = g_pts[si[aa.w]];
        float* o = g_adf + s * 28;
        ((float4*)o)[0] = make_float4(b0.x, b0.y, b0.z, b0.w);
        ((float4*)o)[1] = make_float4(b1.x, b1.y, a0.x, a0.y);
        ((float4*)o)[2] = make_float4(a0.z, a0.w, a1.x, a1.y);
        ((float4*)o)[3] = make_float4(d_ref(P0,Q0), d_ref(P0,Q1), d_ref(P0,Q2), d_ref(P0,Q3));
        ((float4*)o)[4] = make_float4(d_ref(P1,Q0), d_ref(P1,Q1), d_ref(P1,Q2), d_ref(P1,Q3));
        ((float4*)o)[5] = make_float4(d_ref(P2,Q0), d_ref(P2,Q1), d_ref(P2,Q2), d_ref(P2,Q3));
        ((float4*)o)[6] = make_float4(d_ref(P3,Q0), d_ref(P3,Q1), d_ref(P3,Q2), d_ref(P3,Q3));
    }
}

// ---------------- gemm1: y = adf @ {Ww|Wb} + {bw|bb}, thread per (s,ch) ----------------
__global__ void __launch_bounds__(256) gemm1_kernel(
    const float* __restrict__ Ww, const float* __restrict__ bw,
    const float* __restrict__ Wb, const float* __restrict__ bb) {
    int tid = blockIdx.x * blockDim.x + threadIdx.x;
    int ch = tid & 63, s = tid >> 6;
    float aw = bw[ch], ab = bb[ch];
    const float* a = g_adf + s * 28;
#pragma unroll
    for (int c = 0; c < 28; c++) {
        float av = a[c];
        aw = fmaf(av, Ww[c * 64 + ch], aw);
        ab = fmaf(av, Wb[c * 64 + ch], ab);
    }
    g_y[s * 128 + ch]      = aw;
    g_y[s * 128 + 64 + ch] = ab;
}

// ---------------- statspw1: BN stats (w & b) + gate + leaky, 2 channels/block ----------------
__global__ void __launch_bounds__(256) statspw1_kernel(
    const float* __restrict__ gw, const float* __restrict__ betaw,
    const float* __restrict__ gb, const float* __restrict__ betab,
    const float* __restrict__ feature, const int* __restrict__ si) {
    __shared__ float2 red[256], red2[256];
    __shared__ float  stats[8];
    int ch2 = blockIdx.x * 2, tid = threadIdx.x;
    float2 vw[16], vb[16];
    float2 sw = make_float2(0.f, 0.f), s2w = make_float2(0.f, 0.f);
    float2 sb = make_float2(0.f, 0.f), s2b = make_float2(0.f, 0.f);
#pragma unroll
    for (int i = 0; i < 16; i++) {
        int r = i * 256 + tid;
        float2 w = *(const float2*)(g_y + (size_t)r * 128 + ch2);
        float2 b = *(const float2*)(g_y + (size_t)r * 128 + 64 + ch2);
        vw[i] = w; vb[i] = b;
        sw.x += w.x; sw.y += w.y; s2w.x = fmaf(w.x, w.x, s2w.x); s2w.y = fmaf(w.y, w.y, s2w.y);
        sb.x += b.x; sb.y += b.y; s2b.x = fmaf(b.x, b.x, s2b.x); s2b.y = fmaf(b.y, b.y, s2b.y);
    }
    red[tid] = sw; red2[tid] = s2w; __syncthreads();
    for (int st = 128; st > 0; st >>= 1) {
        if (tid < st) {
            red[tid].x += red[tid + st].x;  red[tid].y += red[tid + st].y;
            red2[tid].x += red2[tid + st].x; red2[tid].y += red2[tid + st].y;
        }
        __syncthreads();
    }
    if (tid == 0) {
        float mu0 = red[0].x / (float)S_PTS, mu1 = red[0].y / (float)S_PTS;
        stats[0] = mu0; stats[1] = mu1;
        stats[2] = rsqrtf(red2[0].x / (float)S_PTS - mu0 * mu0 + 1e-5f);
        stats[3] = rsqrtf(red2[0].y / (float)S_PTS - mu1 * mu1 + 1e-5f);
    }
    __syncthreads();
    red[tid] = sb; red2[tid] = s2b; __syncthreads();
    for (int st = 128; st > 0; st >>= 1) {
        if (tid < st) {
            red[tid].x += red[tid + st].x;  red[tid].y += red[tid + st].y;
            red2[tid].x += red2[tid + st].x; red2[tid].y += red2[tid + st].y;
        }
        __syncthreads();
    }
    if (tid == 0) {
        float mu0 = red[0].x / (float)S_PTS, mu1 = red[0].y / (float)S_PTS;
        stats[4] = mu0; stats[5] = mu1;
        stats[6] = rsqrtf(red2[0].x / (float)S_PTS - mu0 * mu0 + 1e-5f);
        stats[7] = rsqrtf(red2[0].y / (float)S_PTS - mu1 * mu1 + 1e-5f);
    }
    __syncthreads();
    float muw0 = stats[0], muw1 = stats[1], rsw0 = stats[2], rsw1 = stats[3];
    float mub0 = stats[4], mub1 = stats[5], rsb0 = stats[6], rsb1 = stats[7];
    float gw0 = gw[ch2], gw1 = gw[ch2 + 1], bew0 = betaw[ch2], bew1 = betaw[ch2 + 1];
    float gb0 = gb[ch2], gb1 = gb[ch2 + 1], beb0 = betab[ch2], beb1 = betab[ch2 + 1];
#pragma unroll
    for (int i = 0; i < 16; i++) {
        int r = i * 256 + tid;
        float2 f = *(const float2*)(feature + (size_t)si[r] * 64 + ch2);
        float w0 = (vw[i].x - muw0) * rsw0 * gw0 + bew0;
        float w1 = (vw[i].y - muw1) * rsw1 * gw1 + bew1;
        float b0 = (vb[i].x - mub0) * rsb0 * gb0 + beb0;
        float b1 = (vb[i].y - mub1) * rsb1 * gb1 + beb1;
        g_fmT[(size_t)ch2 * S_PTS + r]       = leaky(fmaf(f.x, w0, b0));
        g_fmT[(size_t)(ch2 + 1) * S_PTS + r] = leaky(fmaf(f.y, w1, b1));
    }
}

// ---------------- GEMM2: z = [fm | adf] @ Wo + bo ----------------
__global__ void gemm2_kernel(const float* __restrict__ Wo, const float* __restrict__ bo) {
    int tid = blockIdx.x * blockDim.x + threadIdx.x;
    int ch = tid & 127, s = tid >> 7;
    if (s >= S_PTS) return;
    float acc = bo[ch];
#pragma unroll
    for (int c = 0; c < 64; c++) acc = fmaf(g_fmT[c * S_PTS + s], Wo[c * 128 + ch], acc);
    const float* a = g_adf + s * 28;
#pragma unroll
    for (int c = 0; c < 28; c++) acc = fmaf(a[c], Wo[(64 + c) * 128 + ch], acc);
    g_z[s * 128 + ch] = acc;
}

// ---------------- bnpw2: BN stats + affine + leaky, 4 channels/block, float4 I/O ----------------
__global__ void __launch_bounds__(256) bnpw2_kernel(const float* __restrict__ go,
                                                    const float* __restrict__ betao,
                                                    float* __restrict__ out_feat) {
    __shared__ float4 red[256], red2[256];
    __shared__ float4 stats[2];
    int ch4 = blockIdx.x * 4, tid = threadIdx.x;
    float4 v[16];
    float4 s  = make_float4(0.f, 0.f, 0.f, 0.f);
    float4 s2 = make_float4(0.f, 0.f, 0.f, 0.f);
#pragma unroll
    for (int i = 0; i < 16; i++) {
        int r = i * 256 + tid;
        float4 val = *(const float4*)(g_z + (size_t)r * 128 + ch4);
        v[i] = val;
        s.x += val.x; s.y += val.y; s.z += val.z; s.w += val.w;
        s2.x = fmaf(val.x, val.x, s2.x); s2.y = fmaf(val.y, val.y, s2.y);
        s2.z = fmaf(val.z, val.z, s2.z); s2.w = fmaf(val.w, val.w, s2.w);
    }
    red[tid] = s; red2[tid] = s2;
    __syncthreads();
    for (int st = 128; st > 0; st >>= 1) {
        if (tid < st) {
            float4 a = red[tid + st], a2 = red2[tid + st];
            red[tid].x += a.x; red[tid].y += a.y; red[tid].z += a.z; red[tid].w += a.w;
            red2[tid].x += a2.x; red2[tid].y += a2.y; red2[tid].z += a2.z; red2[tid].w += a2.w;
        }
        __syncthreads();
    }
    if (tid == 0) {
        float4 sum = red[0], sum2 = red2[0];
        float4 mu = make_float4(sum.x / S_PTS, sum.y / S_PTS, sum.z / S_PTS, sum.w / S_PTS);
        stats[0] = mu;
        stats[1] = make_float4(rsqrtf(sum2.x / S_PTS - mu.x * mu.x + 1e-5f),
                               rsqrtf(sum2.y / S_PTS - mu.y * mu.y + 1e-5f),
                               rsqrtf(sum2.z / S_PTS - mu.z * mu.z + 1e-5f),
                               rsqrtf(sum2.w / S_PTS - mu.w * mu.w + 1e-5f));
    }
    __syncthreads();
    float4 mu = stats[0], rs = stats[1];
    float4 g  = *(const float4*)(go + ch4);
    float4 be = *(const float4*)(betao + ch4);
#pragma unroll
    for (int i = 0; i < 16; i++) {
        int r = i * 256 + tid;
        float4 val = v[i];
        float4 o;
        o.x = leaky((val.x - mu.x) * rs.x * g.x + be.x);
        o.y = leaky((val.y - mu.y) * rs.y * g.y + be.y);
        o.z = leaky((val.z - mu.z) * rs.z * g.z + be.z);
        o.w = leaky((val.w - mu.w) * rs.w * g.w + be.w);
        *(float4*)(out_feat + (size_t)r * 128 + ch4) = o;
    }
}

// ---------------- launch ----------------
extern "C" void kernel_launch(void* const* d_in, const int* in_sizes, int n_in,
                              void* d_out, int out_size) {
    const float* xyz     = (const float*)d_in[0];
    const float* feature = (const float*)d_in[1];
    const int*   si      = (const int*)  d_in[2];
    const float* Ww    = (const float*)d_in[3];
    const float* bw    = (const float*)d_in[4];
    const float* gw    = (const float*)d_in[5];
    const float* betaw = (const float*)d_in[6];
    const float* Wb    = (const float*)d_in[7];
    const float* bb    = (const float*)d_in[8];
    const float* gb    = (const float*)d_in[9];
    const float* betab = (const float*)d_in[10];
    const float* Wo    = (const float*)d_in[11];
    const float* bo    = (const float*)d_in[12];
    const float* go    = (const float*)d_in[13];
    const float* betao = (const float*)d_in[14];

    float* out        = (float*)d_out;
    float* out_xyz_s  = out;                                  // 4096*3
    float* out_feat   = out + S_PTS * 3;                      // 4096*128
    float* out_rf     = out_feat + S_PTS * 128;               // 4096*16*28
    float* out_ni     = out_rf + (size_t)S_PTS * KNN * 28;    // 4096*16

    prep_kernel<<<(N_PTS + 255) / 256, 256>>>(xyz, si, out_xyz_s);
    scan_kernel<<<1, NBB>>>();
    scatter_kernel<<<(N_PTS + S_PTS) / 256, 256>>>();
    knn_kernel<<<1024, 256>>>(out_ni);                         // 8192 warps
    rf_adf_kernel<<<1040, 256>>>(out_rf, si);
    gemm1_kernel<<<(S_PTS * 64) / 256, 256>>>(Ww, bw, Wb, bb);
    statspw1_kernel<<<32, 256>>>(gw, betaw, gb, betab, feature, si);
    gemm2_kernel<<<(S_PTS * 128) / 256, 256>>>(Wo, bo);
    bnpw2_kernel<<<32, 256>>>(go, betao, out_feat);
}